// round 12
// baseline (speedup 1.0000x reference)
#include <cuda_runtime.h>
#include <cuda_fp16.h>
#include <cstdint>
#include <cstddef>

#define Bsz 4
#define Tseq 2048
#define Dm 512
#define Hh 8
#define FFd 2048
#define NLAYER 4
#define ROWS (Bsz*Tseq)   /* 8192 */

// ---------------- scratch (device globals; no allocations allowed) ----------
__device__ __align__(128) float g_x [ROWS*Dm];
__device__ __align__(128) float g_y [ROWS*Dm];
__device__ __align__(128) __half g_q [ROWS*3*Dm];
__device__ __align__(128) __half g_xa[ROWS*Dm];
__device__ __align__(128) __half g_a [ROWS*Dm];
__device__ __align__(128) __half g_f [ROWS*FFd];
__device__ __align__(128) __half g_wq[NLAYER*3*Dm*Dm];
__device__ __align__(128) __half g_wo[NLAYER*Dm*Dm];
__device__ __align__(128) __half g_w1[NLAYER*FFd*Dm];
__device__ __align__(128) __half g_w2[NLAYER*Dm*FFd];

// ---------------- helpers ----------------------------------------------------
__device__ __forceinline__ void cp16(uint32_t s, const void* g) {
    asm volatile("cp.async.cg.shared.global [%0], [%1], 16;" :: "r"(s), "l"(g));
}
__device__ __forceinline__ void cp16z(uint32_t s, const void* g, int sz) {
    asm volatile("cp.async.cg.shared.global [%0], [%1], 16, %2;" :: "r"(s), "l"(g), "r"(sz));
}
__device__ __forceinline__ void cp_commit() {
    asm volatile("cp.async.commit_group;" ::: "memory");
}
template<int N> __device__ __forceinline__ void cp_wait() {
    asm volatile("cp.async.wait_group %0;" :: "n"(N) : "memory");
}
__device__ __forceinline__ void ldsm4(uint32_t* r, uint32_t addr) {
    asm volatile("ldmatrix.sync.aligned.m8n8.x4.shared.b16 {%0,%1,%2,%3}, [%4];"
                 : "=r"(r[0]), "=r"(r[1]), "=r"(r[2]), "=r"(r[3]) : "r"(addr));
}
__device__ __forceinline__ void ldsm4t(uint32_t* r, uint32_t addr) {
    asm volatile("ldmatrix.sync.aligned.m8n8.x4.trans.shared.b16 {%0,%1,%2,%3}, [%4];"
                 : "=r"(r[0]), "=r"(r[1]), "=r"(r[2]), "=r"(r[3]) : "r"(addr));
}
__device__ __forceinline__ void mma16816(float* c, const uint32_t* a, const uint32_t* b) {
    asm volatile(
        "mma.sync.aligned.m16n8k16.row.col.f32.f16.f16.f32 "
        "{%0,%1,%2,%3}, {%4,%5,%6,%7}, {%8,%9}, {%0,%1,%2,%3};"
        : "+f"(c[0]), "+f"(c[1]), "+f"(c[2]), "+f"(c[3])
        : "r"(a[0]), "r"(a[1]), "r"(a[2]), "r"(a[3]), "r"(b[0]), "r"(b[1]));
}
__device__ __forceinline__ uint32_t packh2(float a, float b) {
    __half2 h = __floats2half2_rn(a, b);
    return *(uint32_t*)&h;
}

// ---------------- weight fp32 -> fp16 convert --------------------------------
__global__ __launch_bounds__(256)
void cvt4_kernel(const float* __restrict__ w, __half* __restrict__ h, int n4) {
    int i = blockIdx.x * 256 + threadIdx.x;
    if (i < n4) {
        float4 v = ((const float4*)w)[i];
        ((__half2*)h)[i*2]     = __floats2half2_rn(v.x, v.y);
        ((__half2*)h)[i*2 + 1] = __floats2half2_rn(v.z, v.w);
    }
}

// ---------------- HMMA GEMM: C[M,N] = A[M,K] @ W[N,K]^T ----------------------
// BM=128, BN=128, BK=32, 128 threads (4 warps, warp tile 64x64), 3-stage
// cp.async, 3 CTAs/SM for bubble-filling.
#define AROW 80
#define A_TILE (128*AROW)            /* 10240 */
#define B_TILE (128*AROW)            /* 10240 */
#define STAGE_B (A_TILE + B_TILE)    /* 20480 */
#define NSTAGE 3
#define GS_TOTAL (NSTAGE*STAGE_B)    /* 61440 per CTA */

__device__ __forceinline__ void gload(uint32_t st,
    const __half* __restrict__ A, const __half* __restrict__ B,
    int bm, int bn, int K, int k0, int tid)
{
    #pragma unroll
    for (int i = 0; i < 4; i++) {
        int idx = tid + i * 128;
        int row = idx >> 2, c = idx & 3;
        cp16(st + (uint32_t)(row * AROW + c * 16), A + (size_t)(bm + row) * K + k0 + c * 8);
    }
    #pragma unroll
    for (int i = 0; i < 4; i++) {
        int idx = tid + i * 128;
        int row = idx >> 2, c = idx & 3;
        cp16(st + A_TILE + (uint32_t)(row * AROW + c * 16), B + (size_t)(bn + row) * K + k0 + c * 8);
    }
    cp_commit();
}

template<int MODE>
__global__ __launch_bounds__(128, 3)
void tc_gemm(const __half* __restrict__ A, const __half* __restrict__ B,
             const float* __restrict__ bias, const float* __restrict__ res,
             float* __restrict__ Cf, __half* __restrict__ Ch,
             int M, int N, int K)
{
    extern __shared__ __align__(128) char smem[];
    uint32_t sb = (uint32_t)__cvta_generic_to_shared(smem);
    int tid = threadIdx.x;
    int wid = tid >> 5, lane = tid & 31;
    int bn = blockIdx.x * 128, bm = blockIdx.y * 128;
    int wm = (wid & 1) * 64;
    int wn = (wid >> 1) * 64;

    float acc[4][8][4];
    #pragma unroll
    for (int i = 0; i < 4; i++)
        #pragma unroll
        for (int j = 0; j < 8; j++)
            #pragma unroll
            for (int r = 0; r < 4; r++) acc[i][j][r] = 0.f;

    const int C = K >> 5;
    gload(sb,           A, B, bm, bn, K, 0,  tid);
    gload(sb + STAGE_B, A, B, bm, bn, K, 32, tid);

    uint32_t a_row = (uint32_t)(lane & 15);
    uint32_t a_koff = (uint32_t)((lane >> 4) * 16);
    uint32_t b_row = (uint32_t)((lane & 7) + ((lane >> 4) << 3));
    uint32_t b_koff = (uint32_t)(((lane >> 3) & 1) * 16);

    for (int c = 0; c < C; c++) {
        if (c + 1 < C) cp_wait<1>(); else cp_wait<0>();
        __syncthreads();
        if (c + 2 < C)
            gload(sb + ((c + 2) % NSTAGE) * STAGE_B, A, B, bm, bn, K, (c + 2) * 32, tid);

        uint32_t sa = sb + (c % NSTAGE) * STAGE_B;
        #pragma unroll
        for (int kk = 0; kk < 2; kk++) {
            uint32_t kb = (uint32_t)(kk * 32);
            uint32_t af[4][4];
            #pragma unroll
            for (int mt = 0; mt < 4; mt++)
                ldsm4(af[mt], sa + (wm + mt*16 + a_row) * AROW + kb + a_koff);
            #pragma unroll
            for (int ng = 0; ng < 4; ng++) {
                uint32_t bf[4];
                ldsm4(bf, sa + A_TILE + (wn + ng*16 + b_row) * AROW + kb + b_koff);
                #pragma unroll
                for (int mt = 0; mt < 4; mt++)
                    #pragma unroll
                    for (int half = 0; half < 2; half++)
                        mma16816(acc[mt][ng*2 + half], af[mt], &bf[half*2]);
            }
        }
    }

    #pragma unroll
    for (int mt = 0; mt < 4; mt++) {
        int m0 = bm + wm + mt*16 + (lane >> 2);
        #pragma unroll
        for (int nt = 0; nt < 8; nt++) {
            int n = bn + wn + nt*8 + (lane & 3)*2;
            float bx = bias[n], by = bias[n+1];
            #pragma unroll
            for (int h = 0; h < 2; h++) {
                int m = m0 + h*8;
                float v0 = acc[mt][nt][h*2]   + bx;
                float v1 = acc[mt][nt][h*2+1] + by;
                size_t idx = (size_t)m * N + n;
                if (MODE == 1) {
                    float2 rv = *(const float2*)&res[idx];
                    v0 += rv.x; v1 += rv.y;
                }
                if (MODE == 2 || MODE == 3) {
                    if (MODE == 2) { v0 = fmaxf(v0, 0.f); v1 = fmaxf(v1, 0.f); }
                    *(__half2*)(Ch + idx) = __floats2half2_rn(v0, v1);
                } else {
                    *(float2*)&Cf[idx] = make_float2(v0, v1);
                }
            }
        }
    }
}

// ---------------- flash banded attention (fp16, register softmax) ------------
#define OFF_Q  0
#define OFF_K0 9216
#define OFF_V0 18432
#define OFF_K1 27648
#define OFF_V1 36864
#define ATT_SMEM 46080

__global__ __launch_bounds__(128, 1)
void attn_flash(const __half* __restrict__ q, __half* __restrict__ outp)
{
    extern __shared__ __align__(128) char smraw[];
    uint32_t sb = (uint32_t)__cvta_generic_to_shared(smraw);

    int tid = threadIdx.x;
    int wid = tid >> 5, lane = tid & 31;
    int b = blockIdx.z, h = blockIdx.y;
    int qstart = blockIdx.x << 6;
    size_t rowbase = (size_t)b * Tseq;
    int wm = wid * 16;

    uint32_t a_row = (uint32_t)(lane & 15);
    uint32_t a_koff = (uint32_t)((lane >> 4) * 16);
    uint32_t b_row = (uint32_t)((lane & 7) + ((lane >> 4) << 3));
    uint32_t b_koff = (uint32_t)(((lane >> 3) & 1) * 16);

    int fi = tid >> 3;
    int seg = tid & 7;

    #pragma unroll
    for (int r = 0; r < 4; r++) {
        int qi = fi + r*16;
        cp16(sb + OFF_Q + qi*144 + seg*16,
             q + (rowbase + qstart + qi)*1536 + h*64 + seg*8);
    }
    #pragma unroll
    for (int r = 0; r < 4; r++) {
        int kj = fi + r*16;
        int ka = qstart - 128 + kj;
        int kc = ka < 0 ? 0 : (ka >= Tseq ? Tseq-1 : ka);
        int ok = (ka >= 0 && ka < Tseq) ? 16 : 0;
        cp16z(sb + OFF_K0 + kj*144 + seg*16,
              q + (rowbase + kc)*1536 + 512 + h*64 + seg*8, ok);
        cp16z(sb + OFF_V0 + kj*144 + seg*16,
              q + (rowbase + kc)*1536 + 1024 + h*64 + seg*8, ok);
    }
    cp_commit();

    const float scale = 0.125f;
    uint32_t af[4][4];
    float m_run[2] = {-1e30f, -1e30f};
    float l_run[2] = {0.f, 0.f};
    float oacc[8][4];
    #pragma unroll
    for (int nt = 0; nt < 8; nt++)
        #pragma unroll
        for (int r = 0; r < 4; r++) oacc[nt][r] = 0.f;

    for (int kb = 0; kb < 5; kb++) {
        cp_wait<0>();
        __syncthreads();
        if (kb == 0) {
            #pragma unroll
            for (int ks = 0; ks < 4; ks++)
                ldsm4(af[ks], sb + OFF_Q + (wm + a_row)*144 + ks*32 + a_koff);
        }
        if (kb < 4) {
            uint32_t kd = (kb + 1) & 1 ? OFF_K1 : OFF_K0;
            uint32_t vd = (kb + 1) & 1 ? OFF_V1 : OFF_V0;
            #pragma unroll
            for (int r = 0; r < 4; r++) {
                int kj = fi + r*16;
                int ka = qstart - 128 + (kb+1)*64 + kj;
                int kc = ka < 0 ? 0 : (ka >= Tseq ? Tseq-1 : ka);
                int ok = (ka >= 0 && ka < Tseq) ? 16 : 0;
                cp16z(sb + kd + kj*144 + seg*16,
                      q + (rowbase + kc)*1536 + 512 + h*64 + seg*8, ok);
                cp16z(sb + vd + kj*144 + seg*16,
                      q + (rowbase + kc)*1536 + 1024 + h*64 + seg*8, ok);
            }
            cp_commit();
        }

        uint32_t kbuf = sb + (kb & 1 ? OFF_K1 : OFF_K0);
        uint32_t vbuf = sb + (kb & 1 ? OFF_V1 : OFF_V0);

        float sacc[8][4];
        #pragma unroll
        for (int nt = 0; nt < 8; nt++)
            #pragma unroll
            for (int r = 0; r < 4; r++) sacc[nt][r] = 0.f;

        #pragma unroll
        for (int ks = 0; ks < 4; ks++) {
            #pragma unroll
            for (int ng = 0; ng < 4; ng++) {
                uint32_t bf[4];
                ldsm4(bf, kbuf + (ng*16 + b_row)*144 + ks*32 + b_koff);
                mma16816(sacc[ng*2],     af[ks], bf);
                mma16816(sacc[ng*2 + 1], af[ks], &bf[2]);
            }
        }

        #pragma unroll
        for (int nt = 0; nt < 8; nt++)
            #pragma unroll
            for (int r = 0; r < 4; r++) {
                int qi   = wm + (lane >> 2) + (r >> 1)*8;
                int kidx = kb*64 + nt*8 + (lane & 3)*2 + (r & 1);
                int ka   = qstart - 128 + kidx;
                int delta = kidx - qi;
                bool ok = (delta >= 0) && (delta <= 256) && (ka >= 0) && (ka < Tseq);
                sacc[nt][r] = ok ? sacc[nt][r] * scale : -1e30f;
            }

        #pragma unroll
        for (int hr = 0; hr < 2; hr++) {
            float mb = -1e30f;
            #pragma unroll
            for (int nt = 0; nt < 8; nt++) {
                mb = fmaxf(mb, sacc[nt][hr*2]);
                mb = fmaxf(mb, sacc[nt][hr*2 + 1]);
            }
            mb = fmaxf(mb, __shfl_xor_sync(0xffffffffu, mb, 1));
            mb = fmaxf(mb, __shfl_xor_sync(0xffffffffu, mb, 2));
            float m_new = fmaxf(m_run[hr], mb);
            float factor = __expf(m_run[hr] - m_new);
            float psum = 0.f;
            #pragma unroll
            for (int nt = 0; nt < 8; nt++)
                #pragma unroll
                for (int j = 0; j < 2; j++) {
                    float s = sacc[nt][hr*2 + j];
                    float p = (s > -1e29f) ? __expf(s - m_new) : 0.f;
                    sacc[nt][hr*2 + j] = p;
                    psum += p;
                }
            psum += __shfl_xor_sync(0xffffffffu, psum, 1);
            psum += __shfl_xor_sync(0xffffffffu, psum, 2);
            l_run[hr] = l_run[hr] * factor + psum;
            m_run[hr] = m_new;
            #pragma unroll
            for (int nt = 0; nt < 8; nt++)
                #pragma unroll
                for (int j = 0; j < 2; j++)
                    oacc[nt][hr*2 + j] *= factor;
        }

        uint32_t pf[4][4];
        #pragma unroll
        for (int ks = 0; ks < 4; ks++) {
            pf[ks][0] = packh2(sacc[2*ks][0],     sacc[2*ks][1]);
            pf[ks][1] = packh2(sacc[2*ks][2],     sacc[2*ks][3]);
            pf[ks][2] = packh2(sacc[2*ks + 1][0], sacc[2*ks + 1][1]);
            pf[ks][3] = packh2(sacc[2*ks + 1][2], sacc[2*ks + 1][3]);
        }

        #pragma unroll
        for (int ks = 0; ks < 4; ks++) {
            #pragma unroll
            for (int dn = 0; dn < 4; dn++) {
                uint32_t bf[4];
                ldsm4t(bf, vbuf + (ks*16 + a_row)*144 + dn*32 + a_koff);
                mma16816(oacc[dn*2],     pf[ks], bf);
                mma16816(oacc[dn*2 + 1], pf[ks], &bf[2]);
            }
        }
    }

    #pragma unroll
    for (int hr = 0; hr < 2; hr++) {
        float rs = 1.0f / l_run[hr];
        int qi = qstart + wm + (lane >> 2) + hr*8;
        #pragma unroll
        for (int nt = 0; nt < 8; nt++) {
            int d = nt*8 + (lane & 3)*2;
            size_t idx = (rowbase + qi)*512 + h*64 + d;
            *(__half2*)(outp + idx) =
                __floats2half2_rn(oacc[nt][hr*2] * rs, oacc[nt][hr*2 + 1] * rs);
        }
    }
}

// ---------------- LayerNorm (+ optional fp16 output) -------------------------
__global__ __launch_bounds__(256)
void ln_kernel(const float* __restrict__ in, const float* __restrict__ gam,
               const float* __restrict__ bet, float* __restrict__ out,
               __half* __restrict__ oh)
{
    int row = blockIdx.x, tid = threadIdx.x;
    const float* p = in + (size_t)row * 512;
    float x0 = p[tid], x1 = p[tid + 256];
    float s = x0 + x1, q = x0*x0 + x1*x1;
    #pragma unroll
    for (int o = 16; o > 0; o >>= 1) {
        s += __shfl_xor_sync(0xffffffffu, s, o);
        q += __shfl_xor_sync(0xffffffffu, q, o);
    }
    __shared__ float ss[8], sq[8];
    int w = tid >> 5, l = tid & 31;
    if (l == 0) { ss[w] = s; sq[w] = q; }
    __syncthreads();
    float ts = 0.f, tq = 0.f;
    #pragma unroll
    for (int i = 0; i < 8; i++) { ts += ss[i]; tq += sq[i]; }
    float mean = ts * (1.0f/512.0f);
    float var  = tq * (1.0f/512.0f) - mean*mean;
    float inv  = rsqrtf(var + 1e-5f);
    float v0 = (x0 - mean) * inv * gam[tid]       + bet[tid];
    float v1 = (x1 - mean) * inv * gam[tid + 256] + bet[tid + 256];
    float* o = out + (size_t)row * 512;
    o[tid]       = v0;
    o[tid + 256] = v1;
    if (oh) {
        oh[(size_t)row*512 + tid]       = __float2half(v0);
        oh[(size_t)row*512 + tid + 256] = __float2half(v1);
    }
}

// ---------------- input projection ------------------------------------------
__global__ __launch_bounds__(128)
void inproj_kernel(const float* __restrict__ feat, const float* __restrict__ w,
                   const float* __restrict__ bias, const float* __restrict__ pe,
                   float* __restrict__ out, __half* __restrict__ oh)
{
    int row = blockIdx.x;
    int t = row & (Tseq - 1);
    __shared__ float f[32];
    if (threadIdx.x < 32) f[threadIdx.x] = feat[(size_t)row*32 + threadIdx.x];
    __syncthreads();
    int d0 = threadIdx.x * 4;
    float a[4];
    #pragma unroll
    for (int j = 0; j < 4; j++) a[j] = bias[d0 + j];
    #pragma unroll
    for (int j = 0; j < 4; j++) {
        const float4* wp = (const float4*)(w + (size_t)(d0 + j) * 32);
        #pragma unroll
        for (int k4 = 0; k4 < 8; k4++) {
            float4 wv = wp[k4];
            a[j] += wv.x*f[k4*4] + wv.y*f[k4*4+1] + wv.z*f[k4*4+2] + wv.w*f[k4*4+3];
        }
    }
    float4 pev = *(const float4*)(pe + (size_t)t*512 + d0);
    float4 r = make_float4(a[0]+pev.x, a[1]+pev.y, a[2]+pev.z, a[3]+pev.w);
    *(float4*)(out + (size_t)row*512 + d0) = r;
    *(__half2*)(oh + (size_t)row*512 + d0)     = __floats2half2_rn(r.x, r.y);
    *(__half2*)(oh + (size_t)row*512 + d0 + 2) = __floats2half2_rn(r.z, r.w);
}

// ---------------- launch ----------------------------------------------------
extern "C" void kernel_launch(void* const* d_in, const int* in_sizes, int n_in,
                              void* d_out, int out_size)
{
    const float* feat   = (const float*)d_in[0];
    const float* proj_w = (const float*)d_in[2];
    const float* proj_b = (const float*)d_in[3];
    const float* pe     = (const float*)d_in[4];
    const float* qkv_w  = (const float*)d_in[5];
    const float* qkv_b  = (const float*)d_in[6];
    const float* out_w  = (const float*)d_in[7];
    const float* out_b  = (const float*)d_in[8];
    const float* ff1_w  = (const float*)d_in[9];
    const float* ff1_b  = (const float*)d_in[10];
    const float* ff2_w  = (const float*)d_in[11];
    const float* ff2_b  = (const float*)d_in[12];
    const float* ln1_g  = (const float*)d_in[13];
    const float* ln1_b  = (const float*)d_in[14];
    const float* ln2_g  = (const float*)d_in[15];
    const float* ln2_b  = (const float*)d_in[16];

    float *x, *y;
    __half *q, *xa, *a, *f, *wq, *wo, *w1, *w2;
    cudaGetSymbolAddress((void**)&x,  g_x);
    cudaGetSymbolAddress((void**)&y,  g_y);
    cudaGetSymbolAddress((void**)&q,  g_q);
    cudaGetSymbolAddress((void**)&xa, g_xa);
    cudaGetSymbolAddress((void**)&a,  g_a);
    cudaGetSymbolAddress((void**)&f,  g_f);
    cudaGetSymbolAddress((void**)&wq, g_wq);
    cudaGetSymbolAddress((void**)&wo, g_wo);
    cudaGetSymbolAddress((void**)&w1, g_w1);
    cudaGetSymbolAddress((void**)&w2, g_w2);

    cudaFuncSetAttribute(attn_flash, cudaFuncAttributeMaxDynamicSharedMemorySize, ATT_SMEM);
    cudaFuncSetAttribute(tc_gemm<0>, cudaFuncAttributeMaxDynamicSharedMemorySize, GS_TOTAL);
    cudaFuncSetAttribute(tc_gemm<1>, cudaFuncAttributeMaxDynamicSharedMemorySize, GS_TOTAL);
    cudaFuncSetAttribute(tc_gemm<2>, cudaFuncAttributeMaxDynamicSharedMemorySize, GS_TOTAL);
    cudaFuncSetAttribute(tc_gemm<3>, cudaFuncAttributeMaxDynamicSharedMemorySize, GS_TOTAL);

    {
        int n4;
        n4 = NLAYER*3*Dm*Dm/4; cvt4_kernel<<<(n4+255)/256,256>>>(qkv_w, wq, n4);
        n4 = NLAYER*Dm*Dm/4;   cvt4_kernel<<<(n4+255)/256,256>>>(out_w, wo, n4);
        n4 = NLAYER*FFd*Dm/4;  cvt4_kernel<<<(n4+255)/256,256>>>(ff1_w, w1, n4);
        n4 = NLAYER*Dm*FFd/4;  cvt4_kernel<<<(n4+255)/256,256>>>(ff2_w, w2, n4);
    }

    inproj_kernel<<<ROWS, 128>>>(feat, proj_w, proj_b, pe, x, xa);

    for (int l = 0; l < NLAYER; l++) {
        // QKV -> fp16
        tc_gemm<3><<<dim3(3*Dm/128, ROWS/128), 128, GS_TOTAL>>>(
            xa, wq + (size_t)l*3*Dm*Dm, qkv_b + (size_t)l*3*Dm, nullptr,
            nullptr, q, ROWS, 3*Dm, Dm);
        // flash banded attention -> a (fp16)
        attn_flash<<<dim3(Tseq/64, Hh, Bsz), 128, ATT_SMEM>>>(q, a);
        // out proj + residual(x) -> y
        tc_gemm<1><<<dim3(Dm/128, ROWS/128), 128, GS_TOTAL>>>(
            a, wo + (size_t)l*Dm*Dm, out_b + (size_t)l*Dm, x,
            y, nullptr, ROWS, Dm, Dm);
        ln_kernel<<<ROWS, 256>>>(y, ln1_g + (size_t)l*Dm, ln1_b + (size_t)l*Dm, x, xa);
        // FF1 + ReLU -> f (fp16)
        tc_gemm<2><<<dim3(FFd/128, ROWS/128), 128, GS_TOTAL>>>(
            xa, w1 + (size_t)l*FFd*Dm, ff1_b + (size_t)l*FFd, nullptr,
            nullptr, f, ROWS, FFd, Dm);
        // FF2 + residual(x) -> y
        tc_gemm<1><<<dim3(Dm/128, ROWS/128), 128, GS_TOTAL>>>(
            f, w2 + (size_t)l*Dm*FFd, ff2_b + (size_t)l*Dm, x,
            y, nullptr, ROWS, Dm, FFd);
        if (l == NLAYER - 1)
            ln_kernel<<<ROWS, 256>>>(y, ln2_g + (size_t)l*Dm, ln2_b + (size_t)l*Dm,
                                     (float*)d_out, nullptr);
        else
            ln_kernel<<<ROWS, 256>>>(y, ln2_g + (size_t)l*Dm, ln2_b + (size_t)l*Dm, x, xa);
    }
}

// round 13
// speedup vs baseline: 1.0307x; 1.0307x over previous
#include <cuda_runtime.h>
#include <cuda_fp16.h>
#include <cstdint>
#include <cstddef>

#define Bsz 4
#define Tseq 2048
#define Dm 512
#define Hh 8
#define FFd 2048
#define NLAYER 4
#define ROWS (Bsz*Tseq)   /* 8192 */

// ---------------- scratch (device globals; no allocations allowed) ----------
__device__ __align__(128) float g_x [ROWS*Dm];
__device__ __align__(128) __half g_y [ROWS*Dm];
__device__ __align__(128) __half g_q [ROWS*3*Dm];
__device__ __align__(128) __half g_xa[ROWS*Dm];
__device__ __align__(128) __half g_a [ROWS*Dm];
__device__ __align__(128) __half g_f [ROWS*FFd];
__device__ __align__(128) __half g_wq[NLAYER*3*Dm*Dm];
__device__ __align__(128) __half g_wo[NLAYER*Dm*Dm];
__device__ __align__(128) __half g_w1[NLAYER*FFd*Dm];
__device__ __align__(128) __half g_w2[NLAYER*Dm*FFd];

// ---------------- helpers ----------------------------------------------------
__device__ __forceinline__ void cp16(uint32_t s, const void* g) {
    asm volatile("cp.async.cg.shared.global [%0], [%1], 16;" :: "r"(s), "l"(g));
}
__device__ __forceinline__ void cp16z(uint32_t s, const void* g, int sz) {
    asm volatile("cp.async.cg.shared.global [%0], [%1], 16, %2;" :: "r"(s), "l"(g), "r"(sz));
}
__device__ __forceinline__ void cp_commit() {
    asm volatile("cp.async.commit_group;" ::: "memory");
}
template<int N> __device__ __forceinline__ void cp_wait() {
    asm volatile("cp.async.wait_group %0;" :: "n"(N) : "memory");
}
__device__ __forceinline__ void ldsm4(uint32_t* r, uint32_t addr) {
    asm volatile("ldmatrix.sync.aligned.m8n8.x4.shared.b16 {%0,%1,%2,%3}, [%4];"
                 : "=r"(r[0]), "=r"(r[1]), "=r"(r[2]), "=r"(r[3]) : "r"(addr));
}
__device__ __forceinline__ void ldsm4t(uint32_t* r, uint32_t addr) {
    asm volatile("ldmatrix.sync.aligned.m8n8.x4.trans.shared.b16 {%0,%1,%2,%3}, [%4];"
                 : "=r"(r[0]), "=r"(r[1]), "=r"(r[2]), "=r"(r[3]) : "r"(addr));
}
__device__ __forceinline__ void mma16816(float* c, const uint32_t* a, const uint32_t* b) {
    asm volatile(
        "mma.sync.aligned.m16n8k16.row.col.f32.f16.f16.f32 "
        "{%0,%1,%2,%3}, {%4,%5,%6,%7}, {%8,%9}, {%0,%1,%2,%3};"
        : "+f"(c[0]), "+f"(c[1]), "+f"(c[2]), "+f"(c[3])
        : "r"(a[0]), "r"(a[1]), "r"(a[2]), "r"(a[3]), "r"(b[0]), "r"(b[1]));
}
__device__ __forceinline__ uint32_t packh2(float a, float b) {
    __half2 h = __floats2half2_rn(a, b);
    return *(uint32_t*)&h;
}

// ---------------- fused weight fp32 -> fp16 convert (single launch) ----------
#define CV_WQ (NLAYER*3*Dm*Dm/4)               /* 786432 float4s */
#define CV_WO (NLAYER*Dm*Dm/4)                 /* 262144 */
#define CV_W1 (NLAYER*FFd*Dm/4)                /* 1048576 */
#define CV_W2 (NLAYER*Dm*FFd/4)                /* 1048576 */
#define CV_TOTAL (CV_WQ + CV_WO + CV_W1 + CV_W2)

__global__ __launch_bounds__(256)
void cvt_all_kernel(const float* __restrict__ wq, const float* __restrict__ wo,
                    const float* __restrict__ w1, const float* __restrict__ w2,
                    __half* __restrict__ dq, __half* __restrict__ do_,
                    __half* __restrict__ d1, __half* __restrict__ d2)
{
    int i = blockIdx.x * 256 + threadIdx.x;
    if (i >= CV_TOTAL) return;
    const float* src; __half* dst; int j;
    if (i < CV_WQ)                   { src = wq; dst = dq;  j = i; }
    else if (i < CV_WQ+CV_WO)        { src = wo; dst = do_; j = i - CV_WQ; }
    else if (i < CV_WQ+CV_WO+CV_W1)  { src = w1; dst = d1;  j = i - CV_WQ - CV_WO; }
    else                             { src = w2; dst = d2;  j = i - CV_WQ - CV_WO - CV_W1; }
    float4 v = ((const float4*)src)[j];
    ((__half2*)dst)[j*2]     = __floats2half2_rn(v.x, v.y);
    ((__half2*)dst)[j*2 + 1] = __floats2half2_rn(v.z, v.w);
}

// ---------------- HMMA GEMM: C[M,N] = A[M,K] @ W[N,K]^T ----------------------
// BM=128, BN=128, BK=32, 128 threads (4 warps, warp tile 64x64), 4-stage
// cp.async, 2 CTAs/SM.
// MODE 1: Ch = fp16(acc + bias + res)
// MODE 2: Ch = fp16(relu(acc + bias))
// MODE 3: Ch = fp16(acc + bias)
#define AROW 80
#define A_TILE (128*AROW)
#define B_TILE (128*AROW)
#define STAGE_B (A_TILE + B_TILE)
#define NSTAGE 4
#define GS_TOTAL (NSTAGE*STAGE_B)   /* 81920 per CTA */

__device__ __forceinline__ void gload(uint32_t st,
    const __half* __restrict__ A, const __half* __restrict__ B,
    int bm, int bn, int K, int k0, int tid)
{
    #pragma unroll
    for (int i = 0; i < 4; i++) {
        int idx = tid + i * 128;
        int row = idx >> 2, c = idx & 3;
        cp16(st + (uint32_t)(row * AROW + c * 16), A + (size_t)(bm + row) * K + k0 + c * 8);
    }
    #pragma unroll
    for (int i = 0; i < 4; i++) {
        int idx = tid + i * 128;
        int row = idx >> 2, c = idx & 3;
        cp16(st + A_TILE + (uint32_t)(row * AROW + c * 16), B + (size_t)(bn + row) * K + k0 + c * 8);
    }
    cp_commit();
}

template<int MODE>
__global__ __launch_bounds__(128, 2)
void tc_gemm(const __half* __restrict__ A, const __half* __restrict__ B,
             const float* __restrict__ bias, const float* __restrict__ res,
             __half* __restrict__ Ch, int M, int N, int K)
{
    extern __shared__ __align__(128) char smem[];
    uint32_t sb = (uint32_t)__cvta_generic_to_shared(smem);
    int tid = threadIdx.x;
    int wid = tid >> 5, lane = tid & 31;
    int bn = blockIdx.x * 128, bm = blockIdx.y * 128;
    int wm = (wid & 1) * 64;
    int wn = (wid >> 1) * 64;

    float acc[4][8][4];
    #pragma unroll
    for (int i = 0; i < 4; i++)
        #pragma unroll
        for (int j = 0; j < 8; j++)
            #pragma unroll
            for (int r = 0; r < 4; r++) acc[i][j][r] = 0.f;

    const int C = K >> 5;
    gload(sb,             A, B, bm, bn, K, 0,  tid);
    gload(sb +   STAGE_B, A, B, bm, bn, K, 32, tid);
    gload(sb + 2*STAGE_B, A, B, bm, bn, K, 64, tid);

    uint32_t a_row = (uint32_t)(lane & 15);
    uint32_t a_koff = (uint32_t)((lane >> 4) * 16);
    uint32_t b_row = (uint32_t)((lane & 7) + ((lane >> 4) << 3));
    uint32_t b_koff = (uint32_t)(((lane >> 3) & 1) * 16);

    for (int c = 0; c < C; c++) {
        if (c + 2 < C) cp_wait<2>();
        else if (c + 1 < C) cp_wait<1>();
        else cp_wait<0>();
        __syncthreads();
        if (c + 3 < C)
            gload(sb + ((c + 3) % NSTAGE) * STAGE_B, A, B, bm, bn, K, (c + 3) * 32, tid);

        uint32_t sa = sb + (c % NSTAGE) * STAGE_B;
        #pragma unroll
        for (int kk = 0; kk < 2; kk++) {
            uint32_t kb = (uint32_t)(kk * 32);
            uint32_t af[4][4];
            #pragma unroll
            for (int mt = 0; mt < 4; mt++)
                ldsm4(af[mt], sa + (wm + mt*16 + a_row) * AROW + kb + a_koff);
            #pragma unroll
            for (int ng = 0; ng < 4; ng++) {
                uint32_t bf[4];
                ldsm4(bf, sa + A_TILE + (wn + ng*16 + b_row) * AROW + kb + b_koff);
                #pragma unroll
                for (int mt = 0; mt < 4; mt++)
                    #pragma unroll
                    for (int half = 0; half < 2; half++)
                        mma16816(acc[mt][ng*2 + half], af[mt], &bf[half*2]);
            }
        }
    }

    #pragma unroll
    for (int mt = 0; mt < 4; mt++) {
        int m0 = bm + wm + mt*16 + (lane >> 2);
        #pragma unroll
        for (int nt = 0; nt < 8; nt++) {
            int n = bn + wn + nt*8 + (lane & 3)*2;
            float bx = bias[n], by = bias[n+1];
            #pragma unroll
            for (int h = 0; h < 2; h++) {
                int m = m0 + h*8;
                float v0 = acc[mt][nt][h*2]   + bx;
                float v1 = acc[mt][nt][h*2+1] + by;
                size_t idx = (size_t)m * N + n;
                if (MODE == 1) {
                    float2 rv = *(const float2*)&res[idx];
                    v0 += rv.x; v1 += rv.y;
                }
                if (MODE == 2) { v0 = fmaxf(v0, 0.f); v1 = fmaxf(v1, 0.f); }
                *(__half2*)(Ch + idx) = __floats2half2_rn(v0, v1);
            }
        }
    }
}

// ---------------- flash banded attention (fp16, register softmax) ------------
#define OFF_Q  0
#define OFF_K0 9216
#define OFF_V0 18432
#define OFF_K1 27648
#define OFF_V1 36864
#define ATT_SMEM 46080

__global__ __launch_bounds__(128, 2)
void attn_flash(const __half* __restrict__ q, __half* __restrict__ outp)
{
    extern __shared__ __align__(128) char smraw[];
    uint32_t sb = (uint32_t)__cvta_generic_to_shared(smraw);

    int tid = threadIdx.x;
    int wid = tid >> 5, lane = tid & 31;
    int b = blockIdx.z, h = blockIdx.y;
    int qstart = blockIdx.x << 6;
    size_t rowbase = (size_t)b * Tseq;
    int wm = wid * 16;

    uint32_t a_row = (uint32_t)(lane & 15);
    uint32_t a_koff = (uint32_t)((lane >> 4) * 16);
    uint32_t b_row = (uint32_t)((lane & 7) + ((lane >> 4) << 3));
    uint32_t b_koff = (uint32_t)(((lane >> 3) & 1) * 16);

    int fi = tid >> 3;
    int seg = tid & 7;

    #pragma unroll
    for (int r = 0; r < 4; r++) {
        int qi = fi + r*16;
        cp16(sb + OFF_Q + qi*144 + seg*16,
             q + (rowbase + qstart + qi)*1536 + h*64 + seg*8);
    }
    #pragma unroll
    for (int r = 0; r < 4; r++) {
        int kj = fi + r*16;
        int ka = qstart - 128 + kj;
        int kc = ka < 0 ? 0 : (ka >= Tseq ? Tseq-1 : ka);
        int ok = (ka >= 0 && ka < Tseq) ? 16 : 0;
        cp16z(sb + OFF_K0 + kj*144 + seg*16,
              q + (rowbase + kc)*1536 + 512 + h*64 + seg*8, ok);
        cp16z(sb + OFF_V0 + kj*144 + seg*16,
              q + (rowbase + kc)*1536 + 1024 + h*64 + seg*8, ok);
    }
    cp_commit();

    const float scale = 0.125f;
    uint32_t af[4][4];
    float m_run[2] = {-1e30f, -1e30f};
    float l_run[2] = {0.f, 0.f};
    float oacc[8][4];
    #pragma unroll
    for (int nt = 0; nt < 8; nt++)
        #pragma unroll
        for (int r = 0; r < 4; r++) oacc[nt][r] = 0.f;

    for (int kb = 0; kb < 5; kb++) {
        cp_wait<0>();
        __syncthreads();
        if (kb == 0) {
            #pragma unroll
            for (int ks = 0; ks < 4; ks++)
                ldsm4(af[ks], sb + OFF_Q + (wm + a_row)*144 + ks*32 + a_koff);
        }
        if (kb < 4) {
            uint32_t kd = (kb + 1) & 1 ? OFF_K1 : OFF_K0;
            uint32_t vd = (kb + 1) & 1 ? OFF_V1 : OFF_V0;
            #pragma unroll
            for (int r = 0; r < 4; r++) {
                int kj = fi + r*16;
                int ka = qstart - 128 + (kb+1)*64 + kj;
                int kc = ka < 0 ? 0 : (ka >= Tseq ? Tseq-1 : ka);
                int ok = (ka >= 0 && ka < Tseq) ? 16 : 0;
                cp16z(sb + kd + kj*144 + seg*16,
                      q + (rowbase + kc)*1536 + 512 + h*64 + seg*8, ok);
                cp16z(sb + vd + kj*144 + seg*16,
                      q + (rowbase + kc)*1536 + 1024 + h*64 + seg*8, ok);
            }
            cp_commit();
        }

        uint32_t kbuf = sb + (kb & 1 ? OFF_K1 : OFF_K0);
        uint32_t vbuf = sb + (kb & 1 ? OFF_V1 : OFF_V0);

        float sacc[8][4];
        #pragma unroll
        for (int nt = 0; nt < 8; nt++)
            #pragma unroll
            for (int r = 0; r < 4; r++) sacc[nt][r] = 0.f;

        #pragma unroll
        for (int ks = 0; ks < 4; ks++) {
            #pragma unroll
            for (int ng = 0; ng < 4; ng++) {
                uint32_t bf[4];
                ldsm4(bf, kbuf + (ng*16 + b_row)*144 + ks*32 + b_koff);
                mma16816(sacc[ng*2],     af[ks], bf);
                mma16816(sacc[ng*2 + 1], af[ks], &bf[2]);
            }
        }

        #pragma unroll
        for (int nt = 0; nt < 8; nt++)
            #pragma unroll
            for (int r = 0; r < 4; r++) {
                int qi   = wm + (lane >> 2) + (r >> 1)*8;
                int kidx = kb*64 + nt*8 + (lane & 3)*2 + (r & 1);
                int ka   = qstart - 128 + kidx;
                int delta = kidx - qi;
                bool ok = (delta >= 0) && (delta <= 256) && (ka >= 0) && (ka < Tseq);
                sacc[nt][r] = ok ? sacc[nt][r] * scale : -1e30f;
            }

        #pragma unroll
        for (int hr = 0; hr < 2; hr++) {
            float mb = -1e30f;
            #pragma unroll
            for (int nt = 0; nt < 8; nt++) {
                mb = fmaxf(mb, sacc[nt][hr*2]);
                mb = fmaxf(mb, sacc[nt][hr*2 + 1]);
            }
            mb = fmaxf(mb, __shfl_xor_sync(0xffffffffu, mb, 1));
            mb = fmaxf(mb, __shfl_xor_sync(0xffffffffu, mb, 2));
            float m_new = fmaxf(m_run[hr], mb);
            float factor = __expf(m_run[hr] - m_new);
            float psum = 0.f;
            #pragma unroll
            for (int nt = 0; nt < 8; nt++)
                #pragma unroll
                for (int j = 0; j < 2; j++) {
                    float s = sacc[nt][hr*2 + j];
                    float p = (s > -1e29f) ? __expf(s - m_new) : 0.f;
                    sacc[nt][hr*2 + j] = p;
                    psum += p;
                }
            psum += __shfl_xor_sync(0xffffffffu, psum, 1);
            psum += __shfl_xor_sync(0xffffffffu, psum, 2);
            l_run[hr] = l_run[hr] * factor + psum;
            m_run[hr] = m_new;
            #pragma unroll
            for (int nt = 0; nt < 8; nt++)
                #pragma unroll
                for (int j = 0; j < 2; j++)
                    oacc[nt][hr*2 + j] *= factor;
        }

        uint32_t pf[4][4];
        #pragma unroll
        for (int ks = 0; ks < 4; ks++) {
            pf[ks][0] = packh2(sacc[2*ks][0],     sacc[2*ks][1]);
            pf[ks][1] = packh2(sacc[2*ks][2],     sacc[2*ks][3]);
            pf[ks][2] = packh2(sacc[2*ks + 1][0], sacc[2*ks + 1][1]);
            pf[ks][3] = packh2(sacc[2*ks + 1][2], sacc[2*ks + 1][3]);
        }

        #pragma unroll
        for (int ks = 0; ks < 4; ks++) {
            #pragma unroll
            for (int dn = 0; dn < 4; dn++) {
                uint32_t bf[4];
                ldsm4t(bf, vbuf + (ks*16 + a_row)*144 + dn*32 + a_koff);
                mma16816(oacc[dn*2],     pf[ks], bf);
                mma16816(oacc[dn*2 + 1], pf[ks], &bf[2]);
            }
        }
    }

    #pragma unroll
    for (int hr = 0; hr < 2; hr++) {
        float rs = 1.0f / l_run[hr];
        int qi = qstart + wm + (lane >> 2) + hr*8;
        #pragma unroll
        for (int nt = 0; nt < 8; nt++) {
            int d = nt*8 + (lane & 3)*2;
            size_t idx = (rowbase + qi)*512 + h*64 + d;
            *(__half2*)(outp + idx) =
                __floats2half2_rn(oacc[nt][hr*2] * rs, oacc[nt][hr*2 + 1] * rs);
        }
    }
}

// ---------------- LayerNorm (fp16 in; fp32 out + optional fp16 out) ----------
__global__ __launch_bounds__(256)
void ln_kernel(const __half* __restrict__ in, const float* __restrict__ gam,
               const float* __restrict__ bet, float* __restrict__ out,
               __half* __restrict__ oh)
{
    int row = blockIdx.x, tid = threadIdx.x;
    const __half2* p = (const __half2*)(in + (size_t)row * 512);
    float2 a = __half22float2(p[tid]);
    float x0 = a.x, x1 = a.y;
    float s = x0 + x1, q = x0*x0 + x1*x1;
    #pragma unroll
    for (int o = 16; o > 0; o >>= 1) {
        s += __shfl_xor_sync(0xffffffffu, s, o);
        q += __shfl_xor_sync(0xffffffffu, q, o);
    }
    __shared__ float ss[8], sq[8];
    int w = tid >> 5, l = tid & 31;
    if (l == 0) { ss[w] = s; sq[w] = q; }
    __syncthreads();
    float ts = 0.f, tq = 0.f;
    #pragma unroll
    for (int i = 0; i < 8; i++) { ts += ss[i]; tq += sq[i]; }
    float mean = ts * (1.0f/512.0f);
    float var  = tq * (1.0f/512.0f) - mean*mean;
    float inv  = rsqrtf(var + 1e-5f);
    int n = tid * 2;
    float v0 = (x0 - mean) * inv * gam[n]   + bet[n];
    float v1 = (x1 - mean) * inv * gam[n+1] + bet[n+1];
    *(float2*)(out + (size_t)row*512 + n) = make_float2(v0, v1);
    if (oh)
        *(__half2*)(oh + (size_t)row*512 + n) = __floats2half2_rn(v0, v1);
}

// ---------------- input projection ------------------------------------------
__global__ __launch_bounds__(128)
void inproj_kernel(const float* __restrict__ feat, const float* __restrict__ w,
                   const float* __restrict__ bias, const float* __restrict__ pe,
                   float* __restrict__ out, __half* __restrict__ oh)
{
    int row = blockIdx.x;
    int t = row & (Tseq - 1);
    __shared__ float f[32];
    if (threadIdx.x < 32) f[threadIdx.x] = feat[(size_t)row*32 + threadIdx.x];
    __syncthreads();
    int d0 = threadIdx.x * 4;
    float a[4];
    #pragma unroll
    for (int j = 0; j < 4; j++) a[j] = bias[d0 + j];
    #pragma unroll
    for (int j = 0; j < 4; j++) {
        const float4* wp = (const float4*)(w + (size_t)(d0 + j) * 32);
        #pragma unroll
        for (int k4 = 0; k4 < 8; k4++) {
            float4 wv = wp[k4];
            a[j] += wv.x*f[k4*4] + wv.y*f[k4*4+1] + wv.z*f[k4*4+2] + wv.w*f[k4*4+3];
        }
    }
    float4 pev = *(const float4*)(pe + (size_t)t*512 + d0);
    float4 r = make_float4(a[0]+pev.x, a[1]+pev.y, a[2]+pev.z, a[3]+pev.w);
    *(float4*)(out + (size_t)row*512 + d0) = r;
    *(__half2*)(oh + (size_t)row*512 + d0)     = __floats2half2_rn(r.x, r.y);
    *(__half2*)(oh + (size_t)row*512 + d0 + 2) = __floats2half2_rn(r.z, r.w);
}

// ---------------- launch ----------------------------------------------------
extern "C" void kernel_launch(void* const* d_in, const int* in_sizes, int n_in,
                              void* d_out, int out_size)
{
    const float* feat   = (const float*)d_in[0];
    const float* proj_w = (const float*)d_in[2];
    const float* proj_b = (const float*)d_in[3];
    const float* pe     = (const float*)d_in[4];
    const float* qkv_w  = (const float*)d_in[5];
    const float* qkv_b  = (const float*)d_in[6];
    const float* out_w  = (const float*)d_in[7];
    const float* out_b  = (const float*)d_in[8];
    const float* ff1_w  = (const float*)d_in[9];
    const float* ff1_b  = (const float*)d_in[10];
    const float* ff2_w  = (const float*)d_in[11];
    const float* ff2_b  = (const float*)d_in[12];
    const float* ln1_g  = (const float*)d_in[13];
    const float* ln1_b  = (const float*)d_in[14];
    const float* ln2_g  = (const float*)d_in[15];
    const float* ln2_b  = (const float*)d_in[16];

    float *x;
    __half *y, *q, *xa, *a, *f, *wq, *wo, *w1, *w2;
    cudaGetSymbolAddress((void**)&x,  g_x);
    cudaGetSymbolAddress((void**)&y,  g_y);
    cudaGetSymbolAddress((void**)&q,  g_q);
    cudaGetSymbolAddress((void**)&xa, g_xa);
    cudaGetSymbolAddress((void**)&a,  g_a);
    cudaGetSymbolAddress((void**)&f,  g_f);
    cudaGetSymbolAddress((void**)&wq, g_wq);
    cudaGetSymbolAddress((void**)&wo, g_wo);
    cudaGetSymbolAddress((void**)&w1, g_w1);
    cudaGetSymbolAddress((void**)&w2, g_w2);

    cudaFuncSetAttribute(attn_flash, cudaFuncAttributeMaxDynamicSharedMemorySize, ATT_SMEM);
    cudaFuncSetAttribute(tc_gemm<1>, cudaFuncAttributeMaxDynamicSharedMemorySize, GS_TOTAL);
    cudaFuncSetAttribute(tc_gemm<2>, cudaFuncAttributeMaxDynamicSharedMemorySize, GS_TOTAL);
    cudaFuncSetAttribute(tc_gemm<3>, cudaFuncAttributeMaxDynamicSharedMemorySize, GS_TOTAL);

    cvt_all_kernel<<<(CV_TOTAL + 255)/256, 256>>>(qkv_w, out_w, ff1_w, ff2_w,
                                                  wq, wo, w1, w2);

    inproj_kernel<<<ROWS, 128>>>(feat, proj_w, proj_b, pe, x, xa);

    for (int l = 0; l < NLAYER; l++) {
        // QKV -> fp16
        tc_gemm<3><<<dim3(3*Dm/128, ROWS/128), 128, GS_TOTAL>>>(
            xa, wq + (size_t)l*3*Dm*Dm, qkv_b + (size_t)l*3*Dm, nullptr,
            q, ROWS, 3*Dm, Dm);
        // flash banded attention -> a (fp16)
        attn_flash<<<dim3(Tseq/64, Hh, Bsz), 128, ATT_SMEM>>>(q, a);
        // out proj + residual(x) -> y (fp16)
        tc_gemm<1><<<dim3(Dm/128, ROWS/128), 128, GS_TOTAL>>>(
            a, wo + (size_t)l*Dm*Dm, out_b + (size_t)l*Dm, x,
            y, ROWS, Dm, Dm);
        ln_kernel<<<ROWS, 256>>>(y, ln1_g + (size_t)l*Dm, ln1_b + (size_t)l*Dm, x, xa);
        // FF1 + ReLU -> f (fp16)
        tc_gemm<2><<<dim3(FFd/128, ROWS/128), 128, GS_TOTAL>>>(
            xa, w1 + (size_t)l*FFd*Dm, ff1_b + (size_t)l*FFd, nullptr,
            f, ROWS, FFd, Dm);
        // FF2 + residual(x) -> y (fp16)
        tc_gemm<1><<<dim3(Dm/128, ROWS/128), 128, GS_TOTAL>>>(
            f, w2 + (size_t)l*Dm*FFd, ff2_b + (size_t)l*Dm, x,
            y, ROWS, Dm, FFd);
        if (l == NLAYER - 1)
            ln_kernel<<<ROWS, 256>>>(y, ln2_g + (size_t)l*Dm, ln2_b + (size_t)l*Dm,
                                     (float*)d_out, nullptr);
        else
            ln_kernel<<<ROWS, 256>>>(y, ln2_g + (size_t)l*Dm, ln2_b + (size_t)l*Dm, x, xa);
    }
}

// round 14
// speedup vs baseline: 1.0376x; 1.0067x over previous
#include <cuda_runtime.h>
#include <cuda_fp16.h>
#include <cstdint>
#include <cstddef>

#define Bsz 4
#define Tseq 2048
#define Dm 512
#define Hh 8
#define FFd 2048
#define NLAYER 4
#define ROWS (Bsz*Tseq)   /* 8192 */

// ---------------- scratch (device globals; no allocations allowed) ----------
__device__ __align__(128) float g_x [ROWS*Dm];
__device__ __align__(128) float g_y [ROWS*Dm];
__device__ __align__(128) __half g_q [ROWS*3*Dm];
__device__ __align__(128) __half g_xa[ROWS*Dm];
__device__ __align__(128) __half g_a [ROWS*Dm];
__device__ __align__(128) __half g_f [ROWS*FFd];
__device__ __align__(128) __half g_wq[NLAYER*3*Dm*Dm];
__device__ __align__(128) __half g_wo[NLAYER*Dm*Dm];
__device__ __align__(128) __half g_w1[NLAYER*FFd*Dm];
__device__ __align__(128) __half g_w2[NLAYER*Dm*FFd];

// ---------------- helpers ----------------------------------------------------
__device__ __forceinline__ void cp16(uint32_t s, const void* g) {
    asm volatile("cp.async.cg.shared.global [%0], [%1], 16;" :: "r"(s), "l"(g));
}
__device__ __forceinline__ void cp16z(uint32_t s, const void* g, int sz) {
    asm volatile("cp.async.cg.shared.global [%0], [%1], 16, %2;" :: "r"(s), "l"(g), "r"(sz));
}
__device__ __forceinline__ void cp_commit() {
    asm volatile("cp.async.commit_group;" ::: "memory");
}
template<int N> __device__ __forceinline__ void cp_wait() {
    asm volatile("cp.async.wait_group %0;" :: "n"(N) : "memory");
}
__device__ __forceinline__ void ldsm4(uint32_t* r, uint32_t addr) {
    asm volatile("ldmatrix.sync.aligned.m8n8.x4.shared.b16 {%0,%1,%2,%3}, [%4];"
                 : "=r"(r[0]), "=r"(r[1]), "=r"(r[2]), "=r"(r[3]) : "r"(addr));
}
__device__ __forceinline__ void ldsm4t(uint32_t* r, uint32_t addr) {
    asm volatile("ldmatrix.sync.aligned.m8n8.x4.trans.shared.b16 {%0,%1,%2,%3}, [%4];"
                 : "=r"(r[0]), "=r"(r[1]), "=r"(r[2]), "=r"(r[3]) : "r"(addr));
}
__device__ __forceinline__ void mma16816(float* c, const uint32_t* a, const uint32_t* b) {
    asm volatile(
        "mma.sync.aligned.m16n8k16.row.col.f32.f16.f16.f32 "
        "{%0,%1,%2,%3}, {%4,%5,%6,%7}, {%8,%9}, {%0,%1,%2,%3};"
        : "+f"(c[0]), "+f"(c[1]), "+f"(c[2]), "+f"(c[3])
        : "r"(a[0]), "r"(a[1]), "r"(a[2]), "r"(a[3]), "r"(b[0]), "r"(b[1]));
}
__device__ __forceinline__ uint32_t packh2(float a, float b) {
    __half2 h = __floats2half2_rn(a, b);
    return *(uint32_t*)&h;
}

// ---------------- fused weight fp32 -> fp16 convert (single launch) ----------
#define CV_WQ (NLAYER*3*Dm*Dm/4)
#define CV_WO (NLAYER*Dm*Dm/4)
#define CV_W1 (NLAYER*FFd*Dm/4)
#define CV_W2 (NLAYER*Dm*FFd/4)
#define CV_TOTAL (CV_WQ + CV_WO + CV_W1 + CV_W2)

__global__ __launch_bounds__(256)
void cvt_all_kernel(const float* __restrict__ wq, const float* __restrict__ wo,
                    const float* __restrict__ w1, const float* __restrict__ w2,
                    __half* __restrict__ dq, __half* __restrict__ do_,
                    __half* __restrict__ d1, __half* __restrict__ d2)
{
    int i = blockIdx.x * 256 + threadIdx.x;
    if (i >= CV_TOTAL) return;
    const float* src; __half* dst; int j;
    if (i < CV_WQ)                   { src = wq; dst = dq;  j = i; }
    else if (i < CV_WQ+CV_WO)        { src = wo; dst = do_; j = i - CV_WQ; }
    else if (i < CV_WQ+CV_WO+CV_W1)  { src = w1; dst = d1;  j = i - CV_WQ - CV_WO; }
    else                             { src = w2; dst = d2;  j = i - CV_WQ - CV_WO - CV_W1; }
    float4 v = ((const float4*)src)[j];
    ((__half2*)dst)[j*2]     = __floats2half2_rn(v.x, v.y);
    ((__half2*)dst)[j*2 + 1] = __floats2half2_rn(v.z, v.w);
}

// ---------------- HMMA GEMM: C[M,N] = A[M,K] @ W[N,K]^T ----------------------
// BM=128, BN=128, BK=32, 128 threads (4 warps, warp tile 64x64), 4-stage
// cp.async, 2 CTAs/SM.
// MODE 1: Cf = acc + bias + res  (fp32 out)
// MODE 2: Ch = fp16(relu(acc + bias))
// MODE 3: Ch = fp16(acc + bias)
#define AROW 80
#define A_TILE (128*AROW)
#define B_TILE (128*AROW)
#define STAGE_B (A_TILE + B_TILE)
#define NSTAGE 4
#define GS_TOTAL (NSTAGE*STAGE_B)   /* 81920 per CTA */

__device__ __forceinline__ void gload(uint32_t st,
    const __half* __restrict__ A, const __half* __restrict__ B,
    int bm, int bn, int K, int k0, int tid)
{
    #pragma unroll
    for (int i = 0; i < 4; i++) {
        int idx = tid + i * 128;
        int row = idx >> 2, c = idx & 3;
        cp16(st + (uint32_t)(row * AROW + c * 16), A + (size_t)(bm + row) * K + k0 + c * 8);
    }
    #pragma unroll
    for (int i = 0; i < 4; i++) {
        int idx = tid + i * 128;
        int row = idx >> 2, c = idx & 3;
        cp16(st + A_TILE + (uint32_t)(row * AROW + c * 16), B + (size_t)(bn + row) * K + k0 + c * 8);
    }
    cp_commit();
}

template<int MODE>
__global__ __launch_bounds__(128, 2)
void tc_gemm(const __half* __restrict__ A, const __half* __restrict__ B,
             const float* __restrict__ bias, const float* __restrict__ res,
             float* __restrict__ Cf, __half* __restrict__ Ch,
             int M, int N, int K)
{
    extern __shared__ __align__(128) char smem[];
    uint32_t sb = (uint32_t)__cvta_generic_to_shared(smem);
    int tid = threadIdx.x;
    int wid = tid >> 5, lane = tid & 31;
    int bn = blockIdx.x * 128, bm = blockIdx.y * 128;
    int wm = (wid & 1) * 64;
    int wn = (wid >> 1) * 64;

    float acc[4][8][4];
    #pragma unroll
    for (int i = 0; i < 4; i++)
        #pragma unroll
        for (int j = 0; j < 8; j++)
            #pragma unroll
            for (int r = 0; r < 4; r++) acc[i][j][r] = 0.f;

    const int C = K >> 5;
    gload(sb,             A, B, bm, bn, K, 0,  tid);
    gload(sb +   STAGE_B, A, B, bm, bn, K, 32, tid);
    gload(sb + 2*STAGE_B, A, B, bm, bn, K, 64, tid);

    uint32_t a_row = (uint32_t)(lane & 15);
    uint32_t a_koff = (uint32_t)((lane >> 4) * 16);
    uint32_t b_row = (uint32_t)((lane & 7) + ((lane >> 4) << 3));
    uint32_t b_koff = (uint32_t)(((lane >> 3) & 1) * 16);

    for (int c = 0; c < C; c++) {
        if (c + 2 < C) cp_wait<2>();
        else if (c + 1 < C) cp_wait<1>();
        else cp_wait<0>();
        __syncthreads();
        if (c + 3 < C)
            gload(sb + ((c + 3) % NSTAGE) * STAGE_B, A, B, bm, bn, K, (c + 3) * 32, tid);

        uint32_t sa = sb + (c % NSTAGE) * STAGE_B;
        #pragma unroll
        for (int kk = 0; kk < 2; kk++) {
            uint32_t kb = (uint32_t)(kk * 32);
            uint32_t af[4][4];
            #pragma unroll
            for (int mt = 0; mt < 4; mt++)
                ldsm4(af[mt], sa + (wm + mt*16 + a_row) * AROW + kb + a_koff);
            #pragma unroll
            for (int ng = 0; ng < 4; ng++) {
                uint32_t bf[4];
                ldsm4(bf, sa + A_TILE + (wn + ng*16 + b_row) * AROW + kb + b_koff);
                #pragma unroll
                for (int mt = 0; mt < 4; mt++)
                    #pragma unroll
                    for (int half = 0; half < 2; half++)
                        mma16816(acc[mt][ng*2 + half], af[mt], &bf[half*2]);
            }
        }
    }

    #pragma unroll
    for (int mt = 0; mt < 4; mt++) {
        int m0 = bm + wm + mt*16 + (lane >> 2);
        #pragma unroll
        for (int nt = 0; nt < 8; nt++) {
            int n = bn + wn + nt*8 + (lane & 3)*2;
            float bx = bias[n], by = bias[n+1];
            #pragma unroll
            for (int h = 0; h < 2; h++) {
                int m = m0 + h*8;
                float v0 = acc[mt][nt][h*2]   + bx;
                float v1 = acc[mt][nt][h*2+1] + by;
                size_t idx = (size_t)m * N + n;
                if (MODE == 1) {
                    float2 rv = *(const float2*)&res[idx];
                    v0 += rv.x; v1 += rv.y;
                    *(float2*)&Cf[idx] = make_float2(v0, v1);
                } else {
                    if (MODE == 2) { v0 = fmaxf(v0, 0.f); v1 = fmaxf(v1, 0.f); }
                    *(__half2*)(Ch + idx) = __floats2half2_rn(v0, v1);
                }
            }
        }
    }
}

// ---------------- flash banded attention (fp16, register softmax) ------------
// Mask loop skipped for interior key blocks (kb=1,2 with in-range ka).
#define OFF_Q  0
#define OFF_K0 9216
#define OFF_V0 18432
#define OFF_K1 27648
#define OFF_V1 36864
#define ATT_SMEM 46080

__global__ __launch_bounds__(128, 2)
void attn_flash(const __half* __restrict__ q, __half* __restrict__ outp)
{
    extern __shared__ __align__(128) char smraw[];
    uint32_t sb = (uint32_t)__cvta_generic_to_shared(smraw);

    int tid = threadIdx.x;
    int wid = tid >> 5, lane = tid & 31;
    int b = blockIdx.z, h = blockIdx.y;
    int qstart = blockIdx.x << 6;
    size_t rowbase = (size_t)b * Tseq;
    int wm = wid * 16;
    bool edge_tile = (qstart < 128) || (qstart + 320 > Tseq);

    uint32_t a_row = (uint32_t)(lane & 15);
    uint32_t a_koff = (uint32_t)((lane >> 4) * 16);
    uint32_t b_row = (uint32_t)((lane & 7) + ((lane >> 4) << 3));
    uint32_t b_koff = (uint32_t)(((lane >> 3) & 1) * 16);

    int fi = tid >> 3;
    int seg = tid & 7;

    #pragma unroll
    for (int r = 0; r < 4; r++) {
        int qi = fi + r*16;
        cp16(sb + OFF_Q + qi*144 + seg*16,
             q + (rowbase + qstart + qi)*1536 + h*64 + seg*8);
    }
    #pragma unroll
    for (int r = 0; r < 4; r++) {
        int kj = fi + r*16;
        int ka = qstart - 128 + kj;
        int kc = ka < 0 ? 0 : (ka >= Tseq ? Tseq-1 : ka);
        int ok = (ka >= 0 && ka < Tseq) ? 16 : 0;
        cp16z(sb + OFF_K0 + kj*144 + seg*16,
              q + (rowbase + kc)*1536 + 512 + h*64 + seg*8, ok);
        cp16z(sb + OFF_V0 + kj*144 + seg*16,
              q + (rowbase + kc)*1536 + 1024 + h*64 + seg*8, ok);
    }
    cp_commit();

    const float scale = 0.125f;
    uint32_t af[4][4];
    float m_run[2] = {-1e30f, -1e30f};
    float l_run[2] = {0.f, 0.f};
    float oacc[8][4];
    #pragma unroll
    for (int nt = 0; nt < 8; nt++)
        #pragma unroll
        for (int r = 0; r < 4; r++) oacc[nt][r] = 0.f;

    for (int kb = 0; kb < 5; kb++) {
        cp_wait<0>();
        __syncthreads();
        if (kb == 0) {
            #pragma unroll
            for (int ks = 0; ks < 4; ks++)
                ldsm4(af[ks], sb + OFF_Q + (wm + a_row)*144 + ks*32 + a_koff);
        }
        if (kb < 4) {
            uint32_t kd = (kb + 1) & 1 ? OFF_K1 : OFF_K0;
            uint32_t vd = (kb + 1) & 1 ? OFF_V1 : OFF_V0;
            #pragma unroll
            for (int r = 0; r < 4; r++) {
                int kj = fi + r*16;
                int ka = qstart - 128 + (kb+1)*64 + kj;
                int kc = ka < 0 ? 0 : (ka >= Tseq ? Tseq-1 : ka);
                int ok = (ka >= 0 && ka < Tseq) ? 16 : 0;
                cp16z(sb + kd + kj*144 + seg*16,
                      q + (rowbase + kc)*1536 + 512 + h*64 + seg*8, ok);
                cp16z(sb + vd + kj*144 + seg*16,
                      q + (rowbase + kc)*1536 + 1024 + h*64 + seg*8, ok);
            }
            cp_commit();
        }

        uint32_t kbuf = sb + (kb & 1 ? OFF_K1 : OFF_K0);
        uint32_t vbuf = sb + (kb & 1 ? OFF_V1 : OFF_V0);

        float sacc[8][4];
        #pragma unroll
        for (int nt = 0; nt < 8; nt++)
            #pragma unroll
            for (int r = 0; r < 4; r++) sacc[nt][r] = 0.f;

        #pragma unroll
        for (int ks = 0; ks < 4; ks++) {
            #pragma unroll
            for (int ng = 0; ng < 4; ng++) {
                uint32_t bf[4];
                ldsm4(bf, kbuf + (ng*16 + b_row)*144 + ks*32 + b_koff);
                mma16816(sacc[ng*2],     af[ks], bf);
                mma16816(sacc[ng*2 + 1], af[ks], &bf[2]);
            }
        }

        // interior blocks kb=1,2 on non-edge tiles are entirely in-band
        bool need_mask = (kb == 0) | (kb >= 3) | edge_tile;
        if (need_mask) {
            #pragma unroll
            for (int nt = 0; nt < 8; nt++)
                #pragma unroll
                for (int r = 0; r < 4; r++) {
                    int qi   = wm + (lane >> 2) + (r >> 1)*8;
                    int kidx = kb*64 + nt*8 + (lane & 3)*2 + (r & 1);
                    int ka   = qstart - 128 + kidx;
                    int delta = kidx - qi;
                    bool ok = (delta >= 0) && (delta <= 256) && (ka >= 0) && (ka < Tseq);
                    sacc[nt][r] = ok ? sacc[nt][r] * scale : -1e30f;
                }
        } else {
            #pragma unroll
            for (int nt = 0; nt < 8; nt++)
                #pragma unroll
                for (int r = 0; r < 4; r++)
                    sacc[nt][r] *= scale;
        }

        #pragma unroll
        for (int hr = 0; hr < 2; hr++) {
            float mb = -1e30f;
            #pragma unroll
            for (int nt = 0; nt < 8; nt++) {
                mb = fmaxf(mb, sacc[nt][hr*2]);
                mb = fmaxf(mb, sacc[nt][hr*2 + 1]);
            }
            mb = fmaxf(mb, __shfl_xor_sync(0xffffffffu, mb, 1));
            mb = fmaxf(mb, __shfl_xor_sync(0xffffffffu, mb, 2));
            float m_new = fmaxf(m_run[hr], mb);
            float factor = __expf(m_run[hr] - m_new);
            float psum = 0.f;
            #pragma unroll
            for (int nt = 0; nt < 8; nt++)
                #pragma unroll
                for (int j = 0; j < 2; j++) {
                    float s = sacc[nt][hr*2 + j];
                    float p = (s > -1e29f) ? __expf(s - m_new) : 0.f;
                    sacc[nt][hr*2 + j] = p;
                    psum += p;
                }
            psum += __shfl_xor_sync(0xffffffffu, psum, 1);
            psum += __shfl_xor_sync(0xffffffffu, psum, 2);
            l_run[hr] = l_run[hr] * factor + psum;
            m_run[hr] = m_new;
            #pragma unroll
            for (int nt = 0; nt < 8; nt++)
                #pragma unroll
                for (int j = 0; j < 2; j++)
                    oacc[nt][hr*2 + j] *= factor;
        }

        uint32_t pf[4][4];
        #pragma unroll
        for (int ks = 0; ks < 4; ks++) {
            pf[ks][0] = packh2(sacc[2*ks][0],     sacc[2*ks][1]);
            pf[ks][1] = packh2(sacc[2*ks][2],     sacc[2*ks][3]);
            pf[ks][2] = packh2(sacc[2*ks + 1][0], sacc[2*ks + 1][1]);
            pf[ks][3] = packh2(sacc[2*ks + 1][2], sacc[2*ks + 1][3]);
        }

        #pragma unroll
        for (int ks = 0; ks < 4; ks++) {
            #pragma unroll
            for (int dn = 0; dn < 4; dn++) {
                uint32_t bf[4];
                ldsm4t(bf, vbuf + (ks*16 + a_row)*144 + dn*32 + a_koff);
                mma16816(oacc[dn*2],     pf[ks], bf);
                mma16816(oacc[dn*2 + 1], pf[ks], &bf[2]);
            }
        }
    }

    #pragma unroll
    for (int hr = 0; hr < 2; hr++) {
        float rs = 1.0f / l_run[hr];
        int qi = qstart + wm + (lane >> 2) + hr*8;
        #pragma unroll
        for (int nt = 0; nt < 8; nt++) {
            int d = nt*8 + (lane & 3)*2;
            size_t idx = (rowbase + qi)*512 + h*64 + d;
            *(__half2*)(outp + idx) =
                __floats2half2_rn(oacc[nt][hr*2] * rs, oacc[nt][hr*2 + 1] * rs);
        }
    }
}

// ---------------- LayerNorm (fp32 in; fp32 out + optional fp16 out) ----------
__global__ __launch_bounds__(256)
void ln_kernel(const float* __restrict__ in, const float* __restrict__ gam,
               const float* __restrict__ bet, float* __restrict__ out,
               __half* __restrict__ oh)
{
    int row = blockIdx.x, tid = threadIdx.x;
    const float* p = in + (size_t)row * 512;
    float x0 = p[tid], x1 = p[tid + 256];
    float s = x0 + x1, q = x0*x0 + x1*x1;
    #pragma unroll
    for (int o = 16; o > 0; o >>= 1) {
        s += __shfl_xor_sync(0xffffffffu, s, o);
        q += __shfl_xor_sync(0xffffffffu, q, o);
    }
    __shared__ float ss[8], sq[8];
    int w = tid >> 5, l = tid & 31;
    if (l == 0) { ss[w] = s; sq[w] = q; }
    __syncthreads();
    float ts = 0.f, tq = 0.f;
    #pragma unroll
    for (int i = 0; i < 8; i++) { ts += ss[i]; tq += sq[i]; }
    float mean = ts * (1.0f/512.0f);
    float var  = tq * (1.0f/512.0f) - mean*mean;
    float inv  = rsqrtf(var + 1e-5f);
    float v0 = (x0 - mean) * inv * gam[tid]       + bet[tid];
    float v1 = (x1 - mean) * inv * gam[tid + 256] + bet[tid + 256];
    float* o = out + (size_t)row * 512;
    o[tid]       = v0;
    o[tid + 256] = v1;
    if (oh) {
        oh[(size_t)row*512 + tid]       = __float2half(v0);
        oh[(size_t)row*512 + tid + 256] = __float2half(v1);
    }
}

// ---------------- input projection ------------------------------------------
__global__ __launch_bounds__(128)
void inproj_kernel(const float* __restrict__ feat, const float* __restrict__ w,
                   const float* __restrict__ bias, const float* __restrict__ pe,
                   float* __restrict__ out, __half* __restrict__ oh)
{
    int row = blockIdx.x;
    int t = row & (Tseq - 1);
    __shared__ float f[32];
    if (threadIdx.x < 32) f[threadIdx.x] = feat[(size_t)row*32 + threadIdx.x];
    __syncthreads();
    int d0 = threadIdx.x * 4;
    float a[4];
    #pragma unroll
    for (int j = 0; j < 4; j++) a[j] = bias[d0 + j];
    #pragma unroll
    for (int j = 0; j < 4; j++) {
        const float4* wp = (const float4*)(w + (size_t)(d0 + j) * 32);
        #pragma unroll
        for (int k4 = 0; k4 < 8; k4++) {
            float4 wv = wp[k4];
            a[j] += wv.x*f[k4*4] + wv.y*f[k4*4+1] + wv.z*f[k4*4+2] + wv.w*f[k4*4+3];
        }
    }
    float4 pev = *(const float4*)(pe + (size_t)t*512 + d0);
    float4 r = make_float4(a[0]+pev.x, a[1]+pev.y, a[2]+pev.z, a[3]+pev.w);
    *(float4*)(out + (size_t)row*512 + d0) = r;
    *(__half2*)(oh + (size_t)row*512 + d0)     = __floats2half2_rn(r.x, r.y);
    *(__half2*)(oh + (size_t)row*512 + d0 + 2) = __floats2half2_rn(r.z, r.w);
}

// ---------------- launch ----------------------------------------------------
extern "C" void kernel_launch(void* const* d_in, const int* in_sizes, int n_in,
                              void* d_out, int out_size)
{
    const float* feat   = (const float*)d_in[0];
    const float* proj_w = (const float*)d_in[2];
    const float* proj_b = (const float*)d_in[3];
    const float* pe     = (const float*)d_in[4];
    const float* qkv_w  = (const float*)d_in[5];
    const float* qkv_b  = (const float*)d_in[6];
    const float* out_w  = (const float*)d_in[7];
    const float* out_b  = (const float*)d_in[8];
    const float* ff1_w  = (const float*)d_in[9];
    const float* ff1_b  = (const float*)d_in[10];
    const float* ff2_w  = (const float*)d_in[11];
    const float* ff2_b  = (const float*)d_in[12];
    const float* ln1_g  = (const float*)d_in[13];
    const float* ln1_b  = (const float*)d_in[14];
    const float* ln2_g  = (const float*)d_in[15];
    const float* ln2_b  = (const float*)d_in[16];

    float *x, *y;
    __half *q, *xa, *a, *f, *wq, *wo, *w1, *w2;
    cudaGetSymbolAddress((void**)&x,  g_x);
    cudaGetSymbolAddress((void**)&y,  g_y);
    cudaGetSymbolAddress((void**)&q,  g_q);
    cudaGetSymbolAddress((void**)&xa, g_xa);
    cudaGetSymbolAddress((void**)&a,  g_a);
    cudaGetSymbolAddress((void**)&f,  g_f);
    cudaGetSymbolAddress((void**)&wq, g_wq);
    cudaGetSymbolAddress((void**)&wo, g_wo);
    cudaGetSymbolAddress((void**)&w1, g_w1);
    cudaGetSymbolAddress((void**)&w2, g_w2);

    cudaFuncSetAttribute(attn_flash, cudaFuncAttributeMaxDynamicSharedMemorySize, ATT_SMEM);
    cudaFuncSetAttribute(tc_gemm<1>, cudaFuncAttributeMaxDynamicSharedMemorySize, GS_TOTAL);
    cudaFuncSetAttribute(tc_gemm<2>, cudaFuncAttributeMaxDynamicSharedMemorySize, GS_TOTAL);
    cudaFuncSetAttribute(tc_gemm<3>, cudaFuncAttributeMaxDynamicSharedMemorySize, GS_TOTAL);

    cvt_all_kernel<<<(CV_TOTAL + 255)/256, 256>>>(qkv_w, out_w, ff1_w, ff2_w,
                                                  wq, wo, w1, w2);

    inproj_kernel<<<ROWS, 128>>>(feat, proj_w, proj_b, pe, x, xa);

    for (int l = 0; l < NLAYER; l++) {
        // QKV -> fp16
        tc_gemm<3><<<dim3(3*Dm/128, ROWS/128), 128, GS_TOTAL>>>(
            xa, wq + (size_t)l*3*Dm*Dm, qkv_b + (size_t)l*3*Dm, nullptr,
            nullptr, q, ROWS, 3*Dm, Dm);
        // flash banded attention -> a (fp16)
        attn_flash<<<dim3(Tseq/64, Hh, Bsz), 128, ATT_SMEM>>>(q, a);
        // out proj + residual(x) -> y (fp32)
        tc_gemm<1><<<dim3(Dm/128, ROWS/128), 128, GS_TOTAL>>>(
            a, wo + (size_t)l*Dm*Dm, out_b + (size_t)l*Dm, x,
            y, nullptr, ROWS, Dm, Dm);
        ln_kernel<<<ROWS, 256>>>(y, ln1_g + (size_t)l*Dm, ln1_b + (size_t)l*Dm, x, xa);
        // FF1 + ReLU -> f (fp16)
        tc_gemm<2><<<dim3(FFd/128, ROWS/128), 128, GS_TOTAL>>>(
            xa, w1 + (size_t)l*FFd*Dm, ff1_b + (size_t)l*FFd, nullptr,
            nullptr, f, ROWS, FFd, Dm);
        // FF2 + residual(x) -> y (fp32)
        tc_gemm<1><<<dim3(Dm/128, ROWS/128), 128, GS_TOTAL>>>(
            f, w2 + (size_t)l*Dm*FFd, ff2_b + (size_t)l*Dm, x,
            y, nullptr, ROWS, Dm, FFd);
        if (l == NLAYER - 1)
            ln_kernel<<<ROWS, 256>>>(y, ln2_g + (size_t)l*Dm, ln2_b + (size_t)l*Dm,
                                     (float*)d_out, nullptr);
        else
            ln_kernel<<<ROWS, 256>>>(y, ln2_g + (size_t)l*Dm, ln2_b + (size_t)l*Dm, x, xa);
    }
}

// round 15
// speedup vs baseline: 1.0749x; 1.0360x over previous
#include <cuda_runtime.h>
#include <cuda_fp16.h>
#include <cstdint>
#include <cstddef>

#define Bsz 4
#define Tseq 2048
#define Dm 512
#define Hh 8
#define FFd 2048
#define NLAYER 4
#define ROWS (Bsz*Tseq)   /* 8192 */

// ---------------- scratch (device globals; no allocations allowed) ----------
__device__ __align__(128) float g_x [ROWS*Dm];
__device__ __align__(128) float g_y [ROWS*Dm];
__device__ __align__(128) __half g_q [ROWS*3*Dm];
__device__ __align__(128) __half g_xa[ROWS*Dm];
__device__ __align__(128) __half g_a [ROWS*Dm];
__device__ __align__(128) __half g_f [ROWS*FFd];
__device__ __align__(128) __half g_wq[NLAYER*3*Dm*Dm];
__device__ __align__(128) __half g_wo[NLAYER*Dm*Dm];
__device__ __align__(128) __half g_w1[NLAYER*FFd*Dm];
__device__ __align__(128) __half g_w2[NLAYER*Dm*FFd];

// ---------------- helpers ----------------------------------------------------
__device__ __forceinline__ void cp16(uint32_t s, const void* g) {
    asm volatile("cp.async.cg.shared.global [%0], [%1], 16;" :: "r"(s), "l"(g));
}
__device__ __forceinline__ void cp16z(uint32_t s, const void* g, int sz) {
    asm volatile("cp.async.cg.shared.global [%0], [%1], 16, %2;" :: "r"(s), "l"(g), "r"(sz));
}
__device__ __forceinline__ void cp_commit() {
    asm volatile("cp.async.commit_group;" ::: "memory");
}
template<int N> __device__ __forceinline__ void cp_wait() {
    asm volatile("cp.async.wait_group %0;" :: "n"(N) : "memory");
}
__device__ __forceinline__ void ldsm4(uint32_t* r, uint32_t addr) {
    asm volatile("ldmatrix.sync.aligned.m8n8.x4.shared.b16 {%0,%1,%2,%3}, [%4];"
                 : "=r"(r[0]), "=r"(r[1]), "=r"(r[2]), "=r"(r[3]) : "r"(addr));
}
__device__ __forceinline__ void ldsm4t(uint32_t* r, uint32_t addr) {
    asm volatile("ldmatrix.sync.aligned.m8n8.x4.trans.shared.b16 {%0,%1,%2,%3}, [%4];"
                 : "=r"(r[0]), "=r"(r[1]), "=r"(r[2]), "=r"(r[3]) : "r"(addr));
}
__device__ __forceinline__ void mma16816(float* c, const uint32_t* a, const uint32_t* b) {
    asm volatile(
        "mma.sync.aligned.m16n8k16.row.col.f32.f16.f16.f32 "
        "{%0,%1,%2,%3}, {%4,%5,%6,%7}, {%8,%9}, {%0,%1,%2,%3};"
        : "+f"(c[0]), "+f"(c[1]), "+f"(c[2]), "+f"(c[3])
        : "r"(a[0]), "r"(a[1]), "r"(a[2]), "r"(a[3]), "r"(b[0]), "r"(b[1]));
}
__device__ __forceinline__ uint32_t packh2(float a, float b) {
    __half2 h = __floats2half2_rn(a, b);
    return *(uint32_t*)&h;
}

// ---------------- fused weight fp32 -> fp16 convert (single launch) ----------
#define CV_WQ (NLAYER*3*Dm*Dm/4)
#define CV_WO (NLAYER*Dm*Dm/4)
#define CV_W1 (NLAYER*FFd*Dm/4)
#define CV_W2 (NLAYER*Dm*FFd/4)
#define CV_TOTAL (CV_WQ + CV_WO + CV_W1 + CV_W2)

__global__ __launch_bounds__(256)
void cvt_all_kernel(const float* __restrict__ wq, const float* __restrict__ wo,
                    const float* __restrict__ w1, const float* __restrict__ w2,
                    __half* __restrict__ dq, __half* __restrict__ do_,
                    __half* __restrict__ d1, __half* __restrict__ d2)
{
    int i = blockIdx.x * 256 + threadIdx.x;
    if (i >= CV_TOTAL) return;
    const float* src; __half* dst; int j;
    if (i < CV_WQ)                   { src = wq; dst = dq;  j = i; }
    else if (i < CV_WQ+CV_WO)        { src = wo; dst = do_; j = i - CV_WQ; }
    else if (i < CV_WQ+CV_WO+CV_W1)  { src = w1; dst = d1;  j = i - CV_WQ - CV_WO; }
    else                             { src = w2; dst = d2;  j = i - CV_WQ - CV_WO - CV_W1; }
    float4 v = ((const float4*)src)[j];
    ((__half2*)dst)[j*2]     = __floats2half2_rn(v.x, v.y);
    ((__half2*)dst)[j*2 + 1] = __floats2half2_rn(v.z, v.w);
}

// ---------------- HMMA GEMM: C[M,N] = A[M,K] @ W[N,K]^T ----------------------
// BM=128, BN=128, BK=64, 128 threads (4 warps, warp tile 64x64), 3-stage
// cp.async, 2 CTAs/SM. Halved sync frequency vs BK=32.
// MODE 1: Cf = acc + bias + res  (fp32 out)
// MODE 2: Ch = fp16(relu(acc + bias))
// MODE 3: Ch = fp16(acc + bias)
#define AROW 144                     /* 64 halves (128B) + 16B pad */
#define A_TILE (128*AROW)            /* 18432 */
#define B_TILE (128*AROW)            /* 18432 */
#define STAGE_B (A_TILE + B_TILE)    /* 36864 */
#define NSTAGE 3
#define GS_TOTAL (NSTAGE*STAGE_B)    /* 110592 per CTA */

__device__ __forceinline__ void gload(uint32_t st,
    const __half* __restrict__ A, const __half* __restrict__ B,
    int bm, int bn, int K, int k0, int tid)
{
    #pragma unroll
    for (int i = 0; i < 8; i++) {
        int idx = tid + i * 128;              // 0..1023
        int row = idx >> 3, c = idx & 7;
        cp16(st + (uint32_t)(row * AROW + c * 16), A + (size_t)(bm + row) * K + k0 + c * 8);
    }
    #pragma unroll
    for (int i = 0; i < 8; i++) {
        int idx = tid + i * 128;
        int row = idx >> 3, c = idx & 7;
        cp16(st + A_TILE + (uint32_t)(row * AROW + c * 16), B + (size_t)(bn + row) * K + k0 + c * 8);
    }
    cp_commit();
}

template<int MODE>
__global__ __launch_bounds__(128, 2)
void tc_gemm(const __half* __restrict__ A, const __half* __restrict__ B,
             const float* __restrict__ bias, const float* __restrict__ res,
             float* __restrict__ Cf, __half* __restrict__ Ch,
             int M, int N, int K)
{
    extern __shared__ __align__(128) char smem[];
    uint32_t sb = (uint32_t)__cvta_generic_to_shared(smem);
    int tid = threadIdx.x;
    int wid = tid >> 5, lane = tid & 31;
    int bn = blockIdx.x * 128, bm = blockIdx.y * 128;
    int wm = (wid & 1) * 64;
    int wn = (wid >> 1) * 64;

    float acc[4][8][4];
    #pragma unroll
    for (int i = 0; i < 4; i++)
        #pragma unroll
        for (int j = 0; j < 8; j++)
            #pragma unroll
            for (int r = 0; r < 4; r++) acc[i][j][r] = 0.f;

    const int C = K >> 6;
    gload(sb,           A, B, bm, bn, K, 0,  tid);
    gload(sb + STAGE_B, A, B, bm, bn, K, 64, tid);

    uint32_t a_row = (uint32_t)(lane & 15);
    uint32_t a_koff = (uint32_t)((lane >> 4) * 16);
    uint32_t b_row = (uint32_t)((lane & 7) + ((lane >> 4) << 3));
    uint32_t b_koff = (uint32_t)(((lane >> 3) & 1) * 16);

    for (int c = 0; c < C; c++) {
        if (c + 1 < C) cp_wait<1>(); else cp_wait<0>();
        __syncthreads();
        if (c + 2 < C)
            gload(sb + ((c + 2) % NSTAGE) * STAGE_B, A, B, bm, bn, K, (c + 2) * 64, tid);

        uint32_t sa = sb + (c % NSTAGE) * STAGE_B;
        #pragma unroll
        for (int kk = 0; kk < 4; kk++) {
            uint32_t kb = (uint32_t)(kk * 32);
            uint32_t af[4][4];
            #pragma unroll
            for (int mt = 0; mt < 4; mt++)
                ldsm4(af[mt], sa + (wm + mt*16 + a_row) * AROW + kb + a_koff);
            #pragma unroll
            for (int ng = 0; ng < 4; ng++) {
                uint32_t bf[4];
                ldsm4(bf, sa + A_TILE + (wn + ng*16 + b_row) * AROW + kb + b_koff);
                #pragma unroll
                for (int mt = 0; mt < 4; mt++)
                    #pragma unroll
                    for (int half = 0; half < 2; half++)
                        mma16816(acc[mt][ng*2 + half], af[mt], &bf[half*2]);
            }
        }
    }

    #pragma unroll
    for (int mt = 0; mt < 4; mt++) {
        int m0 = bm + wm + mt*16 + (lane >> 2);
        #pragma unroll
        for (int nt = 0; nt < 8; nt++) {
            int n = bn + wn + nt*8 + (lane & 3)*2;
            float bx = bias[n], by = bias[n+1];
            #pragma unroll
            for (int h = 0; h < 2; h++) {
                int m = m0 + h*8;
                float v0 = acc[mt][nt][h*2]   + bx;
                float v1 = acc[mt][nt][h*2+1] + by;
                size_t idx = (size_t)m * N + n;
                if (MODE == 1) {
                    float2 rv = *(const float2*)&res[idx];
                    v0 += rv.x; v1 += rv.y;
                    *(float2*)&Cf[idx] = make_float2(v0, v1);
                } else {
                    if (MODE == 2) { v0 = fmaxf(v0, 0.f); v1 = fmaxf(v1, 0.f); }
                    *(__half2*)(Ch + idx) = __floats2half2_rn(v0, v1);
                }
            }
        }
    }
}

// ---------------- flash banded attention (fp16, register softmax) ------------
#define OFF_Q  0
#define OFF_K0 9216
#define OFF_V0 18432
#define OFF_K1 27648
#define OFF_V1 36864
#define ATT_SMEM 46080
#define QROW 144

__global__ __launch_bounds__(128, 2)
void attn_flash(const __half* __restrict__ q, __half* __restrict__ outp)
{
    extern __shared__ __align__(128) char smraw[];
    uint32_t sb = (uint32_t)__cvta_generic_to_shared(smraw);

    int tid = threadIdx.x;
    int wid = tid >> 5, lane = tid & 31;
    int b = blockIdx.z, h = blockIdx.y;
    int qstart = blockIdx.x << 6;
    size_t rowbase = (size_t)b * Tseq;
    int wm = wid * 16;
    bool edge_tile = (qstart < 128) || (qstart + 320 > Tseq);

    uint32_t a_row = (uint32_t)(lane & 15);
    uint32_t a_koff = (uint32_t)((lane >> 4) * 16);
    uint32_t b_row = (uint32_t)((lane & 7) + ((lane >> 4) << 3));
    uint32_t b_koff = (uint32_t)(((lane >> 3) & 1) * 16);

    int fi = tid >> 3;
    int seg = tid & 7;

    #pragma unroll
    for (int r = 0; r < 4; r++) {
        int qi = fi + r*16;
        cp16(sb + OFF_Q + qi*QROW + seg*16,
             q + (rowbase + qstart + qi)*1536 + h*64 + seg*8);
    }
    #pragma unroll
    for (int r = 0; r < 4; r++) {
        int kj = fi + r*16;
        int ka = qstart - 128 + kj;
        int kc = ka < 0 ? 0 : (ka >= Tseq ? Tseq-1 : ka);
        int ok = (ka >= 0 && ka < Tseq) ? 16 : 0;
        cp16z(sb + OFF_K0 + kj*QROW + seg*16,
              q + (rowbase + kc)*1536 + 512 + h*64 + seg*8, ok);
        cp16z(sb + OFF_V0 + kj*QROW + seg*16,
              q + (rowbase + kc)*1536 + 1024 + h*64 + seg*8, ok);
    }
    cp_commit();

    const float scale = 0.125f;
    uint32_t af[4][4];
    float m_run[2] = {-1e30f, -1e30f};
    float l_run[2] = {0.f, 0.f};
    float oacc[8][4];
    #pragma unroll
    for (int nt = 0; nt < 8; nt++)
        #pragma unroll
        for (int r = 0; r < 4; r++) oacc[nt][r] = 0.f;

    for (int kb = 0; kb < 5; kb++) {
        cp_wait<0>();
        __syncthreads();
        if (kb == 0) {
            #pragma unroll
            for (int ks = 0; ks < 4; ks++)
                ldsm4(af[ks], sb + OFF_Q + (wm + a_row)*QROW + ks*32 + a_koff);
        }
        if (kb < 4) {
            uint32_t kd = (kb + 1) & 1 ? OFF_K1 : OFF_K0;
            uint32_t vd = (kb + 1) & 1 ? OFF_V1 : OFF_V0;
            #pragma unroll
            for (int r = 0; r < 4; r++) {
                int kj = fi + r*16;
                int ka = qstart - 128 + (kb+1)*64 + kj;
                int kc = ka < 0 ? 0 : (ka >= Tseq ? Tseq-1 : ka);
                int ok = (ka >= 0 && ka < Tseq) ? 16 : 0;
                cp16z(sb + kd + kj*QROW + seg*16,
                      q + (rowbase + kc)*1536 + 512 + h*64 + seg*8, ok);
                cp16z(sb + vd + kj*QROW + seg*16,
                      q + (rowbase + kc)*1536 + 1024 + h*64 + seg*8, ok);
            }
            cp_commit();
        }

        uint32_t kbuf = sb + (kb & 1 ? OFF_K1 : OFF_K0);
        uint32_t vbuf = sb + (kb & 1 ? OFF_V1 : OFF_V0);

        float sacc[8][4];
        #pragma unroll
        for (int nt = 0; nt < 8; nt++)
            #pragma unroll
            for (int r = 0; r < 4; r++) sacc[nt][r] = 0.f;

        #pragma unroll
        for (int ks = 0; ks < 4; ks++) {
            #pragma unroll
            for (int ng = 0; ng < 4; ng++) {
                uint32_t bf[4];
                ldsm4(bf, kbuf + (ng*16 + b_row)*QROW + ks*32 + b_koff);
                mma16816(sacc[ng*2],     af[ks], bf);
                mma16816(sacc[ng*2 + 1], af[ks], &bf[2]);
            }
        }

        bool need_mask = (kb == 0) | (kb >= 3) | edge_tile;
        if (need_mask) {
            #pragma unroll
            for (int nt = 0; nt < 8; nt++)
                #pragma unroll
                for (int r = 0; r < 4; r++) {
                    int qi   = wm + (lane >> 2) + (r >> 1)*8;
                    int kidx = kb*64 + nt*8 + (lane & 3)*2 + (r & 1);
                    int ka   = qstart - 128 + kidx;
                    int delta = kidx - qi;
                    bool ok = (delta >= 0) && (delta <= 256) && (ka >= 0) && (ka < Tseq);
                    sacc[nt][r] = ok ? sacc[nt][r] * scale : -1e30f;
                }
        } else {
            #pragma unroll
            for (int nt = 0; nt < 8; nt++)
                #pragma unroll
                for (int r = 0; r < 4; r++)
                    sacc[nt][r] *= scale;
        }

        #pragma unroll
        for (int hr = 0; hr < 2; hr++) {
            float mb = -1e30f;
            #pragma unroll
            for (int nt = 0; nt < 8; nt++) {
                mb = fmaxf(mb, sacc[nt][hr*2]);
                mb = fmaxf(mb, sacc[nt][hr*2 + 1]);
            }
            mb = fmaxf(mb, __shfl_xor_sync(0xffffffffu, mb, 1));
            mb = fmaxf(mb, __shfl_xor_sync(0xffffffffu, mb, 2));
            float m_new = fmaxf(m_run[hr], mb);
            float factor = __expf(m_run[hr] - m_new);
            float psum = 0.f;
            #pragma unroll
            for (int nt = 0; nt < 8; nt++)
                #pragma unroll
                for (int j = 0; j < 2; j++) {
                    float s = sacc[nt][hr*2 + j];
                    float p = (s > -1e29f) ? __expf(s - m_new) : 0.f;
                    sacc[nt][hr*2 + j] = p;
                    psum += p;
                }
            psum += __shfl_xor_sync(0xffffffffu, psum, 1);
            psum += __shfl_xor_sync(0xffffffffu, psum, 2);
            l_run[hr] = l_run[hr] * factor + psum;
            m_run[hr] = m_new;
            #pragma unroll
            for (int nt = 0; nt < 8; nt++)
                #pragma unroll
                for (int j = 0; j < 2; j++)
                    oacc[nt][hr*2 + j] *= factor;
        }

        uint32_t pf[4][4];
        #pragma unroll
        for (int ks = 0; ks < 4; ks++) {
            pf[ks][0] = packh2(sacc[2*ks][0],     sacc[2*ks][1]);
            pf[ks][1] = packh2(sacc[2*ks][2],     sacc[2*ks][3]);
            pf[ks][2] = packh2(sacc[2*ks + 1][0], sacc[2*ks + 1][1]);
            pf[ks][3] = packh2(sacc[2*ks + 1][2], sacc[2*ks + 1][3]);
        }

        #pragma unroll
        for (int ks = 0; ks < 4; ks++) {
            #pragma unroll
            for (int dn = 0; dn < 4; dn++) {
                uint32_t bf[4];
                ldsm4t(bf, vbuf + (ks*16 + a_row)*QROW + dn*32 + a_koff);
                mma16816(oacc[dn*2],     pf[ks], bf);
                mma16816(oacc[dn*2 + 1], pf[ks], &bf[2]);
            }
        }
    }

    #pragma unroll
    for (int hr = 0; hr < 2; hr++) {
        float rs = 1.0f / l_run[hr];
        int qi = qstart + wm + (lane >> 2) + hr*8;
        #pragma unroll
        for (int nt = 0; nt < 8; nt++) {
            int d = nt*8 + (lane & 3)*2;
            size_t idx = (rowbase + qi)*512 + h*64 + d;
            *(__half2*)(outp + idx) =
                __floats2half2_rn(oacc[nt][hr*2] * rs, oacc[nt][hr*2 + 1] * rs);
        }
    }
}

// ---------------- LayerNorm (fp32 in; fp32 out + optional fp16 out) ----------
__global__ __launch_bounds__(256)
void ln_kernel(const float* __restrict__ in, const float* __restrict__ gam,
               const float* __restrict__ bet, float* __restrict__ out,
               __half* __restrict__ oh)
{
    int row = blockIdx.x, tid = threadIdx.x;
    const float* p = in + (size_t)row * 512;
    float x0 = p[tid], x1 = p[tid + 256];
    float s = x0 + x1, q = x0*x0 + x1*x1;
    #pragma unroll
    for (int o = 16; o > 0; o >>= 1) {
        s += __shfl_xor_sync(0xffffffffu, s, o);
        q += __shfl_xor_sync(0xffffffffu, q, o);
    }
    __shared__ float ss[8], sq[8];
    int w = tid >> 5, l = tid & 31;
    if (l == 0) { ss[w] = s; sq[w] = q; }
    __syncthreads();
    float ts = 0.f, tq = 0.f;
    #pragma unroll
    for (int i = 0; i < 8; i++) { ts += ss[i]; tq += sq[i]; }
    float mean = ts * (1.0f/512.0f);
    float var  = tq * (1.0f/512.0f) - mean*mean;
    float inv  = rsqrtf(var + 1e-5f);
    float v0 = (x0 - mean) * inv * gam[tid]       + bet[tid];
    float v1 = (x1 - mean) * inv * gam[tid + 256] + bet[tid + 256];
    float* o = out + (size_t)row * 512;
    o[tid]       = v0;
    o[tid + 256] = v1;
    if (oh) {
        oh[(size_t)row*512 + tid]       = __float2half(v0);
        oh[(size_t)row*512 + tid + 256] = __float2half(v1);
    }
}

// ---------------- input projection ------------------------------------------
__global__ __launch_bounds__(128)
void inproj_kernel(const float* __restrict__ feat, const float* __restrict__ w,
                   const float* __restrict__ bias, const float* __restrict__ pe,
                   float* __restrict__ out, __half* __restrict__ oh)
{
    int row = blockIdx.x;
    int t = row & (Tseq - 1);
    __shared__ float f[32];
    if (threadIdx.x < 32) f[threadIdx.x] = feat[(size_t)row*32 + threadIdx.x];
    __syncthreads();
    int d0 = threadIdx.x * 4;
    float a[4];
    #pragma unroll
    for (int j = 0; j < 4; j++) a[j] = bias[d0 + j];
    #pragma unroll
    for (int j = 0; j < 4; j++) {
        const float4* wp = (const float4*)(w + (size_t)(d0 + j) * 32);
        #pragma unroll
        for (int k4 = 0; k4 < 8; k4++) {
            float4 wv = wp[k4];
            a[j] += wv.x*f[k4*4] + wv.y*f[k4*4+1] + wv.z*f[k4*4+2] + wv.w*f[k4*4+3];
        }
    }
    float4 pev = *(const float4*)(pe + (size_t)t*512 + d0);
    float4 r = make_float4(a[0]+pev.x, a[1]+pev.y, a[2]+pev.z, a[3]+pev.w);
    *(float4*)(out + (size_t)row*512 + d0) = r;
    *(__half2*)(oh + (size_t)row*512 + d0)     = __floats2half2_rn(r.x, r.y);
    *(__half2*)(oh + (size_t)row*512 + d0 + 2) = __floats2half2_rn(r.z, r.w);
}

// ---------------- launch ----------------------------------------------------
extern "C" void kernel_launch(void* const* d_in, const int* in_sizes, int n_in,
                              void* d_out, int out_size)
{
    const float* feat   = (const float*)d_in[0];
    const float* proj_w = (const float*)d_in[2];
    const float* proj_b = (const float*)d_in[3];
    const float* pe     = (const float*)d_in[4];
    const float* qkv_w  = (const float*)d_in[5];
    const float* qkv_b  = (const float*)d_in[6];
    const float* out_w  = (const float*)d_in[7];
    const float* out_b  = (const float*)d_in[8];
    const float* ff1_w  = (const float*)d_in[9];
    const float* ff1_b  = (const float*)d_in[10];
    const float* ff2_w  = (const float*)d_in[11];
    const float* ff2_b  = (const float*)d_in[12];
    const float* ln1_g  = (const float*)d_in[13];
    const float* ln1_b  = (const float*)d_in[14];
    const float* ln2_g  = (const float*)d_in[15];
    const float* ln2_b  = (const float*)d_in[16];

    float *x, *y;
    __half *q, *xa, *a, *f, *wq, *wo, *w1, *w2;
    cudaGetSymbolAddress((void**)&x,  g_x);
    cudaGetSymbolAddress((void**)&y,  g_y);
    cudaGetSymbolAddress((void**)&q,  g_q);
    cudaGetSymbolAddress((void**)&xa, g_xa);
    cudaGetSymbolAddress((void**)&a,  g_a);
    cudaGetSymbolAddress((void**)&f,  g_f);
    cudaGetSymbolAddress((void**)&wq, g_wq);
    cudaGetSymbolAddress((void**)&wo, g_wo);
    cudaGetSymbolAddress((void**)&w1, g_w1);
    cudaGetSymbolAddress((void**)&w2, g_w2);

    cudaFuncSetAttribute(attn_flash, cudaFuncAttributeMaxDynamicSharedMemorySize, ATT_SMEM);
    cudaFuncSetAttribute(tc_gemm<1>, cudaFuncAttributeMaxDynamicSharedMemorySize, GS_TOTAL);
    cudaFuncSetAttribute(tc_gemm<2>, cudaFuncAttributeMaxDynamicSharedMemorySize, GS_TOTAL);
    cudaFuncSetAttribute(tc_gemm<3>, cudaFuncAttributeMaxDynamicSharedMemorySize, GS_TOTAL);

    cvt_all_kernel<<<(CV_TOTAL + 255)/256, 256>>>(qkv_w, out_w, ff1_w, ff2_w,
                                                  wq, wo, w1, w2);

    inproj_kernel<<<ROWS, 128>>>(feat, proj_w, proj_b, pe, x, xa);

    for (int l = 0; l < NLAYER; l++) {
        // QKV -> fp16
        tc_gemm<3><<<dim3(3*Dm/128, ROWS/128), 128, GS_TOTAL>>>(
            xa, wq + (size_t)l*3*Dm*Dm, qkv_b + (size_t)l*3*Dm, nullptr,
            nullptr, q, ROWS, 3*Dm, Dm);
        // flash banded attention -> a (fp16)
        attn_flash<<<dim3(Tseq/64, Hh, Bsz), 128, ATT_SMEM>>>(q, a);
        // out proj + residual(x) -> y (fp32)
        tc_gemm<1><<<dim3(Dm/128, ROWS/128), 128, GS_TOTAL>>>(
            a, wo + (size_t)l*Dm*Dm, out_b + (size_t)l*Dm, x,
            y, nullptr, ROWS, Dm, Dm);
        ln_kernel<<<ROWS, 256>>>(y, ln1_g + (size_t)l*Dm, ln1_b + (size_t)l*Dm, x, xa);
        // FF1 + ReLU -> f (fp16)
        tc_gemm<2><<<dim3(FFd/128, ROWS/128), 128, GS_TOTAL>>>(
            xa, w1 + (size_t)l*FFd*Dm, ff1_b + (size_t)l*FFd, nullptr,
            nullptr, f, ROWS, FFd, Dm);
        // FF2 + residual(x) -> y (fp32)
        tc_gemm<1><<<dim3(Dm/128, ROWS/128), 128, GS_TOTAL>>>(
            f, w2 + (size_t)l*Dm*FFd, ff2_b + (size_t)l*Dm, x,
            y, nullptr, ROWS, Dm, FFd);
        if (l == NLAYER - 1)
            ln_kernel<<<ROWS, 256>>>(y, ln2_g + (size_t)l*Dm, ln2_b + (size_t)l*Dm,
                                     (float*)d_out, nullptr);
        else
            ln_kernel<<<ROWS, 256>>>(y, ln2_g + (size_t)l*Dm, ln2_b + (size_t)l*Dm, x, xa);
    }
}

// round 16
// speedup vs baseline: 1.0769x; 1.0019x over previous
#include <cuda_runtime.h>
#include <cuda_fp16.h>
#include <cstdint>
#include <cstddef>

#define Bsz 4
#define Tseq 2048
#define Dm 512
#define Hh 8
#define FFd 2048
#define NLAYER 4
#define ROWS (Bsz*Tseq)   /* 8192 */

// ---------------- scratch (device globals; no allocations allowed) ----------
__device__ __align__(128) float g_x [ROWS*Dm];
__device__ __align__(128) float g_y [ROWS*Dm];
__device__ __align__(128) __half g_q [ROWS*3*Dm];
__device__ __align__(128) __half g_xa[ROWS*Dm];
__device__ __align__(128) __half g_a [ROWS*Dm];
__device__ __align__(128) __half g_f [ROWS*FFd];
__device__ __align__(128) __half g_wq[NLAYER*3*Dm*Dm];
__device__ __align__(128) __half g_wo[NLAYER*Dm*Dm];
__device__ __align__(128) __half g_w1[NLAYER*FFd*Dm];
__device__ __align__(128) __half g_w2[NLAYER*Dm*FFd];

// ---------------- helpers ----------------------------------------------------
__device__ __forceinline__ void cp16(uint32_t s, const void* g) {
    asm volatile("cp.async.cg.shared.global [%0], [%1], 16;" :: "r"(s), "l"(g));
}
__device__ __forceinline__ void cp16z(uint32_t s, const void* g, int sz) {
    asm volatile("cp.async.cg.shared.global [%0], [%1], 16, %2;" :: "r"(s), "l"(g), "r"(sz));
}
__device__ __forceinline__ void cp_commit() {
    asm volatile("cp.async.commit_group;" ::: "memory");
}
template<int N> __device__ __forceinline__ void cp_wait() {
    asm volatile("cp.async.wait_group %0;" :: "n"(N) : "memory");
}
__device__ __forceinline__ void ldsm4(uint32_t* r, uint32_t addr) {
    asm volatile("ldmatrix.sync.aligned.m8n8.x4.shared.b16 {%0,%1,%2,%3}, [%4];"
                 : "=r"(r[0]), "=r"(r[1]), "=r"(r[2]), "=r"(r[3]) : "r"(addr));
}
__device__ __forceinline__ void ldsm4t(uint32_t* r, uint32_t addr) {
    asm volatile("ldmatrix.sync.aligned.m8n8.x4.trans.shared.b16 {%0,%1,%2,%3}, [%4];"
                 : "=r"(r[0]), "=r"(r[1]), "=r"(r[2]), "=r"(r[3]) : "r"(addr));
}
__device__ __forceinline__ void mma16816(float* c, const uint32_t* a, const uint32_t* b) {
    asm volatile(
        "mma.sync.aligned.m16n8k16.row.col.f32.f16.f16.f32 "
        "{%0,%1,%2,%3}, {%4,%5,%6,%7}, {%8,%9}, {%0,%1,%2,%3};"
        : "+f"(c[0]), "+f"(c[1]), "+f"(c[2]), "+f"(c[3])
        : "r"(a[0]), "r"(a[1]), "r"(a[2]), "r"(a[3]), "r"(b[0]), "r"(b[1]));
}
__device__ __forceinline__ uint32_t packh2(float a, float b) {
    __half2 h = __floats2half2_rn(a, b);
    return *(uint32_t*)&h;
}

// ---------------- fused weight fp32 -> fp16 convert (single launch) ----------
#define CV_WQ (NLAYER*3*Dm*Dm/4)
#define CV_WO (NLAYER*Dm*Dm/4)
#define CV_W1 (NLAYER*FFd*Dm/4)
#define CV_W2 (NLAYER*Dm*FFd/4)
#define CV_TOTAL (CV_WQ + CV_WO + CV_W1 + CV_W2)

__global__ __launch_bounds__(256)
void cvt_all_kernel(const float* __restrict__ wq, const float* __restrict__ wo,
                    const float* __restrict__ w1, const float* __restrict__ w2,
                    __half* __restrict__ dq, __half* __restrict__ do_,
                    __half* __restrict__ d1, __half* __restrict__ d2)
{
    int i = blockIdx.x * 256 + threadIdx.x;
    if (i >= CV_TOTAL) return;
    const float* src; __half* dst; int j;
    if (i < CV_WQ)                   { src = wq; dst = dq;  j = i; }
    else if (i < CV_WQ+CV_WO)        { src = wo; dst = do_; j = i - CV_WQ; }
    else if (i < CV_WQ+CV_WO+CV_W1)  { src = w1; dst = d1;  j = i - CV_WQ - CV_WO; }
    else                             { src = w2; dst = d2;  j = i - CV_WQ - CV_WO - CV_W1; }
    float4 v = ((const float4*)src)[j];
    ((__half2*)dst)[j*2]     = __floats2half2_rn(v.x, v.y);
    ((__half2*)dst)[j*2 + 1] = __floats2half2_rn(v.z, v.w);
}

// ---------------- HMMA GEMM: C[M,N] = A[M,K] @ W[N,K]^T ----------------------
// BM=128, BN=128, BK=64, 128 threads (4 warps, warp tile 64x64), 3-stage
// cp.async, 2 CTAs/SM, software-pipelined fragment double-buffering.
// MODE 1: Cf = acc + bias + res  (fp32 out)
// MODE 2: Ch = fp16(relu(acc + bias))
// MODE 3: Ch = fp16(acc + bias)
#define AROW 144
#define A_TILE (128*AROW)
#define B_TILE (128*AROW)
#define STAGE_B (A_TILE + B_TILE)
#define NSTAGE 3
#define GS_TOTAL (NSTAGE*STAGE_B)   /* 110592 per CTA */

__device__ __forceinline__ void gload(uint32_t st,
    const __half* __restrict__ A, const __half* __restrict__ B,
    int bm, int bn, int K, int k0, int tid)
{
    #pragma unroll
    for (int i = 0; i < 8; i++) {
        int idx = tid + i * 128;
        int row = idx >> 3, c = idx & 7;
        cp16(st + (uint32_t)(row * AROW + c * 16), A + (size_t)(bm + row) * K + k0 + c * 8);
    }
    #pragma unroll
    for (int i = 0; i < 8; i++) {
        int idx = tid + i * 128;
        int row = idx >> 3, c = idx & 7;
        cp16(st + A_TILE + (uint32_t)(row * AROW + c * 16), B + (size_t)(bn + row) * K + k0 + c * 8);
    }
    cp_commit();
}

template<int MODE>
__global__ __launch_bounds__(128, 2)
void tc_gemm(const __half* __restrict__ A, const __half* __restrict__ B,
             const float* __restrict__ bias, const float* __restrict__ res,
             float* __restrict__ Cf, __half* __restrict__ Ch,
             int M, int N, int K)
{
    extern __shared__ __align__(128) char smem[];
    uint32_t sb = (uint32_t)__cvta_generic_to_shared(smem);
    int tid = threadIdx.x;
    int wid = tid >> 5, lane = tid & 31;
    int bn = blockIdx.x * 128, bm = blockIdx.y * 128;
    int wm = (wid & 1) * 64;
    int wn = (wid >> 1) * 64;

    float acc[4][8][4];
    #pragma unroll
    for (int i = 0; i < 4; i++)
        #pragma unroll
        for (int j = 0; j < 8; j++)
            #pragma unroll
            for (int r = 0; r < 4; r++) acc[i][j][r] = 0.f;

    const int C = K >> 6;
    gload(sb,           A, B, bm, bn, K, 0,  tid);
    gload(sb + STAGE_B, A, B, bm, bn, K, 64, tid);

    uint32_t a_row = (uint32_t)(lane & 15);
    uint32_t a_koff = (uint32_t)((lane >> 4) * 16);
    uint32_t b_row = (uint32_t)((lane & 7) + ((lane >> 4) << 3));
    uint32_t b_koff = (uint32_t)(((lane >> 3) & 1) * 16);

    uint32_t afb[2][4][4], bfb[2][4][4];

    for (int c = 0; c < C; c++) {
        if (c + 1 < C) cp_wait<1>(); else cp_wait<0>();
        __syncthreads();
        if (c + 2 < C)
            gload(sb + ((c + 2) % NSTAGE) * STAGE_B, A, B, bm, bn, K, (c + 2) * 64, tid);

        uint32_t sa = sb + (c % NSTAGE) * STAGE_B;

        // prefetch kk=0 fragments
        #pragma unroll
        for (int mt = 0; mt < 4; mt++)
            ldsm4(afb[0][mt], sa + (wm + mt*16 + a_row) * AROW + a_koff);
        #pragma unroll
        for (int ng = 0; ng < 4; ng++)
            ldsm4(bfb[0][ng], sa + A_TILE + (wn + ng*16 + b_row) * AROW + b_koff);

        #pragma unroll
        for (int kk = 0; kk < 4; kk++) {
            int cur = kk & 1, nxt = cur ^ 1;
            if (kk < 3) {
                uint32_t kb = (uint32_t)((kk + 1) * 32);
                #pragma unroll
                for (int mt = 0; mt < 4; mt++)
                    ldsm4(afb[nxt][mt], sa + (wm + mt*16 + a_row) * AROW + kb + a_koff);
                #pragma unroll
                for (int ng = 0; ng < 4; ng++)
                    ldsm4(bfb[nxt][ng], sa + A_TILE + (wn + ng*16 + b_row) * AROW + kb + b_koff);
            }
            #pragma unroll
            for (int ng = 0; ng < 4; ng++)
                #pragma unroll
                for (int mt = 0; mt < 4; mt++)
                    #pragma unroll
                    for (int half = 0; half < 2; half++)
                        mma16816(acc[mt][ng*2 + half], afb[cur][mt], &bfb[cur][ng][half*2]);
        }
    }

    #pragma unroll
    for (int mt = 0; mt < 4; mt++) {
        int m0 = bm + wm + mt*16 + (lane >> 2);
        #pragma unroll
        for (int nt = 0; nt < 8; nt++) {
            int n = bn + wn + nt*8 + (lane & 3)*2;
            float bx = bias[n], by = bias[n+1];
            #pragma unroll
            for (int h = 0; h < 2; h++) {
                int m = m0 + h*8;
                float v0 = acc[mt][nt][h*2]   + bx;
                float v1 = acc[mt][nt][h*2+1] + by;
                size_t idx = (size_t)m * N + n;
                if (MODE == 1) {
                    float2 rv = *(const float2*)&res[idx];
                    v0 += rv.x; v1 += rv.y;
                    *(float2*)&Cf[idx] = make_float2(v0, v1);
                } else {
                    if (MODE == 2) { v0 = fmaxf(v0, 0.f); v1 = fmaxf(v1, 0.f); }
                    *(__half2*)(Ch + idx) = __floats2half2_rn(v0, v1);
                }
            }
        }
    }
}

// ---------------- flash banded attention (fp16, register softmax) ------------
#define OFF_Q  0
#define OFF_K0 9216
#define OFF_V0 18432
#define OFF_K1 27648
#define OFF_V1 36864
#define ATT_SMEM 46080
#define QROW 144

__global__ __launch_bounds__(128, 2)
void attn_flash(const __half* __restrict__ q, __half* __restrict__ outp)
{
    extern __shared__ __align__(128) char smraw[];
    uint32_t sb = (uint32_t)__cvta_generic_to_shared(smraw);

    int tid = threadIdx.x;
    int wid = tid >> 5, lane = tid & 31;
    int b = blockIdx.z, h = blockIdx.y;
    int qstart = blockIdx.x << 6;
    size_t rowbase = (size_t)b * Tseq;
    int wm = wid * 16;
    bool edge_tile = (qstart < 128) || (qstart + 320 > Tseq);

    uint32_t a_row = (uint32_t)(lane & 15);
    uint32_t a_koff = (uint32_t)((lane >> 4) * 16);
    uint32_t b_row = (uint32_t)((lane & 7) + ((lane >> 4) << 3));
    uint32_t b_koff = (uint32_t)(((lane >> 3) & 1) * 16);

    int fi = tid >> 3;
    int seg = tid & 7;

    #pragma unroll
    for (int r = 0; r < 4; r++) {
        int qi = fi + r*16;
        cp16(sb + OFF_Q + qi*QROW + seg*16,
             q + (rowbase + qstart + qi)*1536 + h*64 + seg*8);
    }
    #pragma unroll
    for (int r = 0; r < 4; r++) {
        int kj = fi + r*16;
        int ka = qstart - 128 + kj;
        int kc = ka < 0 ? 0 : (ka >= Tseq ? Tseq-1 : ka);
        int ok = (ka >= 0 && ka < Tseq) ? 16 : 0;
        cp16z(sb + OFF_K0 + kj*QROW + seg*16,
              q + (rowbase + kc)*1536 + 512 + h*64 + seg*8, ok);
        cp16z(sb + OFF_V0 + kj*QROW + seg*16,
              q + (rowbase + kc)*1536 + 1024 + h*64 + seg*8, ok);
    }
    cp_commit();

    const float scale = 0.125f;
    uint32_t af[4][4];
    float m_run[2] = {-1e30f, -1e30f};
    float l_run[2] = {0.f, 0.f};
    float oacc[8][4];
    #pragma unroll
    for (int nt = 0; nt < 8; nt++)
        #pragma unroll
        for (int r = 0; r < 4; r++) oacc[nt][r] = 0.f;

    for (int kb = 0; kb < 5; kb++) {
        cp_wait<0>();
        __syncthreads();
        if (kb == 0) {
            #pragma unroll
            for (int ks = 0; ks < 4; ks++)
                ldsm4(af[ks], sb + OFF_Q + (wm + a_row)*QROW + ks*32 + a_koff);
        }
        if (kb < 4) {
            uint32_t kd = (kb + 1) & 1 ? OFF_K1 : OFF_K0;
            uint32_t vd = (kb + 1) & 1 ? OFF_V1 : OFF_V0;
            #pragma unroll
            for (int r = 0; r < 4; r++) {
                int kj = fi + r*16;
                int ka = qstart - 128 + (kb+1)*64 + kj;
                int kc = ka < 0 ? 0 : (ka >= Tseq ? Tseq-1 : ka);
                int ok = (ka >= 0 && ka < Tseq) ? 16 : 0;
                cp16z(sb + kd + kj*QROW + seg*16,
                      q + (rowbase + kc)*1536 + 512 + h*64 + seg*8, ok);
                cp16z(sb + vd + kj*QROW + seg*16,
                      q + (rowbase + kc)*1536 + 1024 + h*64 + seg*8, ok);
            }
            cp_commit();
        }

        uint32_t kbuf = sb + (kb & 1 ? OFF_K1 : OFF_K0);
        uint32_t vbuf = sb + (kb & 1 ? OFF_V1 : OFF_V0);

        float sacc[8][4];
        #pragma unroll
        for (int nt = 0; nt < 8; nt++)
            #pragma unroll
            for (int r = 0; r < 4; r++) sacc[nt][r] = 0.f;

        #pragma unroll
        for (int ks = 0; ks < 4; ks++) {
            #pragma unroll
            for (int ng = 0; ng < 4; ng++) {
                uint32_t bf[4];
                ldsm4(bf, kbuf + (ng*16 + b_row)*QROW + ks*32 + b_koff);
                mma16816(sacc[ng*2],     af[ks], bf);
                mma16816(sacc[ng*2 + 1], af[ks], &bf[2]);
            }
        }

        bool need_mask = (kb == 0) | (kb >= 3) | edge_tile;
        if (need_mask) {
            #pragma unroll
            for (int nt = 0; nt < 8; nt++)
                #pragma unroll
                for (int r = 0; r < 4; r++) {
                    int qi   = wm + (lane >> 2) + (r >> 1)*8;
                    int kidx = kb*64 + nt*8 + (lane & 3)*2 + (r & 1);
                    int ka   = qstart - 128 + kidx;
                    int delta = kidx - qi;
                    bool ok = (delta >= 0) && (delta <= 256) && (ka >= 0) && (ka < Tseq);
                    sacc[nt][r] = ok ? sacc[nt][r] * scale : -1e30f;
                }
        } else {
            #pragma unroll
            for (int nt = 0; nt < 8; nt++)
                #pragma unroll
                for (int r = 0; r < 4; r++)
                    sacc[nt][r] *= scale;
        }

        #pragma unroll
        for (int hr = 0; hr < 2; hr++) {
            float mb = -1e30f;
            #pragma unroll
            for (int nt = 0; nt < 8; nt++) {
                mb = fmaxf(mb, sacc[nt][hr*2]);
                mb = fmaxf(mb, sacc[nt][hr*2 + 1]);
            }
            mb = fmaxf(mb, __shfl_xor_sync(0xffffffffu, mb, 1));
            mb = fmaxf(mb, __shfl_xor_sync(0xffffffffu, mb, 2));
            float m_new = fmaxf(m_run[hr], mb);
            float factor = __expf(m_run[hr] - m_new);
            float psum = 0.f;
            #pragma unroll
            for (int nt = 0; nt < 8; nt++)
                #pragma unroll
                for (int j = 0; j < 2; j++) {
                    float s = sacc[nt][hr*2 + j];
                    float p = (s > -1e29f) ? __expf(s - m_new) : 0.f;
                    sacc[nt][hr*2 + j] = p;
                    psum += p;
                }
            psum += __shfl_xor_sync(0xffffffffu, psum, 1);
            psum += __shfl_xor_sync(0xffffffffu, psum, 2);
            l_run[hr] = l_run[hr] * factor + psum;
            m_run[hr] = m_new;
            #pragma unroll
            for (int nt = 0; nt < 8; nt++)
                #pragma unroll
                for (int j = 0; j < 2; j++)
                    oacc[nt][hr*2 + j] *= factor;
        }

        uint32_t pf[4][4];
        #pragma unroll
        for (int ks = 0; ks < 4; ks++) {
            pf[ks][0] = packh2(sacc[2*ks][0],     sacc[2*ks][1]);
            pf[ks][1] = packh2(sacc[2*ks][2],     sacc[2*ks][3]);
            pf[ks][2] = packh2(sacc[2*ks + 1][0], sacc[2*ks + 1][1]);
            pf[ks][3] = packh2(sacc[2*ks + 1][2], sacc[2*ks + 1][3]);
        }

        #pragma unroll
        for (int ks = 0; ks < 4; ks++) {
            #pragma unroll
            for (int dn = 0; dn < 4; dn++) {
                uint32_t bf[4];
                ldsm4t(bf, vbuf + (ks*16 + a_row)*QROW + dn*32 + a_koff);
                mma16816(oacc[dn*2],     pf[ks], bf);
                mma16816(oacc[dn*2 + 1], pf[ks], &bf[2]);
            }
        }
    }

    #pragma unroll
    for (int hr = 0; hr < 2; hr++) {
        float rs = 1.0f / l_run[hr];
        int qi = qstart + wm + (lane >> 2) + hr*8;
        #pragma unroll
        for (int nt = 0; nt < 8; nt++) {
            int d = nt*8 + (lane & 3)*2;
            size_t idx = (rowbase + qi)*512 + h*64 + d;
            *(__half2*)(outp + idx) =
                __floats2half2_rn(oacc[nt][hr*2] * rs, oacc[nt][hr*2 + 1] * rs);
        }
    }
}

// ---------------- LayerNorm (fp32 in; fp32 out + optional fp16 out) ----------
__global__ __launch_bounds__(256)
void ln_kernel(const float* __restrict__ in, const float* __restrict__ gam,
               const float* __restrict__ bet, float* __restrict__ out,
               __half* __restrict__ oh)
{
    int row = blockIdx.x, tid = threadIdx.x;
    const float* p = in + (size_t)row * 512;
    float x0 = p[tid], x1 = p[tid + 256];
    float s = x0 + x1, q = x0*x0 + x1*x1;
    #pragma unroll
    for (int o = 16; o > 0; o >>= 1) {
        s += __shfl_xor_sync(0xffffffffu, s, o);
        q += __shfl_xor_sync(0xffffffffu, q, o);
    }
    __shared__ float ss[8], sq[8];
    int w = tid >> 5, l = tid & 31;
    if (l == 0) { ss[w] = s; sq[w] = q; }
    __syncthreads();
    float ts = 0.f, tq = 0.f;
    #pragma unroll
    for (int i = 0; i < 8; i++) { ts += ss[i]; tq += sq[i]; }
    float mean = ts * (1.0f/512.0f);
    float var  = tq * (1.0f/512.0f) - mean*mean;
    float inv  = rsqrtf(var + 1e-5f);
    float v0 = (x0 - mean) * inv * gam[tid]       + bet[tid];
    float v1 = (x1 - mean) * inv * gam[tid + 256] + bet[tid + 256];
    float* o = out + (size_t)row * 512;
    o[tid]       = v0;
    o[tid + 256] = v1;
    if (oh) {
        oh[(size_t)row*512 + tid]       = __float2half(v0);
        oh[(size_t)row*512 + tid + 256] = __float2half(v1);
    }
}

// ---------------- input projection ------------------------------------------
__global__ __launch_bounds__(128)
void inproj_kernel(const float* __restrict__ feat, const float* __restrict__ w,
                   const float* __restrict__ bias, const float* __restrict__ pe,
                   float* __restrict__ out, __half* __restrict__ oh)
{
    int row = blockIdx.x;
    int t = row & (Tseq - 1);
    __shared__ float f[32];
    if (threadIdx.x < 32) f[threadIdx.x] = feat[(size_t)row*32 + threadIdx.x];
    __syncthreads();
    int d0 = threadIdx.x * 4;
    float a[4];
    #pragma unroll
    for (int j = 0; j < 4; j++) a[j] = bias[d0 + j];
    #pragma unroll
    for (int j = 0; j < 4; j++) {
        const float4* wp = (const float4*)(w + (size_t)(d0 + j) * 32);
        #pragma unroll
        for (int k4 = 0; k4 < 8; k4++) {
            float4 wv = wp[k4];
            a[j] += wv.x*f[k4*4] + wv.y*f[k4*4+1] + wv.z*f[k4*4+2] + wv.w*f[k4*4+3];
        }
    }
    float4 pev = *(const float4*)(pe + (size_t)t*512 + d0);
    float4 r = make_float4(a[0]+pev.x, a[1]+pev.y, a[2]+pev.z, a[3]+pev.w);
    *(float4*)(out + (size_t)row*512 + d0) = r;
    *(__half2*)(oh + (size_t)row*512 + d0)     = __floats2half2_rn(r.x, r.y);
    *(__half2*)(oh + (size_t)row*512 + d0 + 2) = __floats2half2_rn(r.z, r.w);
}

// ---------------- launch ----------------------------------------------------
extern "C" void kernel_launch(void* const* d_in, const int* in_sizes, int n_in,
                              void* d_out, int out_size)
{
    const float* feat   = (const float*)d_in[0];
    const float* proj_w = (const float*)d_in[2];
    const float* proj_b = (const float*)d_in[3];
    const float* pe     = (const float*)d_in[4];
    const float* qkv_w  = (const float*)d_in[5];
    const float* qkv_b  = (const float*)d_in[6];
    const float* out_w  = (const float*)d_in[7];
    const float* out_b  = (const float*)d_in[8];
    const float* ff1_w  = (const float*)d_in[9];
    const float* ff1_b  = (const float*)d_in[10];
    const float* ff2_w  = (const float*)d_in[11];
    const float* ff2_b  = (const float*)d_in[12];
    const float* ln1_g  = (const float*)d_in[13];
    const float* ln1_b  = (const float*)d_in[14];
    const float* ln2_g  = (const float*)d_in[15];
    const float* ln2_b  = (const float*)d_in[16];

    float *x, *y;
    __half *q, *xa, *a, *f, *wq, *wo, *w1, *w2;
    cudaGetSymbolAddress((void**)&x,  g_x);
    cudaGetSymbolAddress((void**)&y,  g_y);
    cudaGetSymbolAddress((void**)&q,  g_q);
    cudaGetSymbolAddress((void**)&xa, g_xa);
    cudaGetSymbolAddress((void**)&a,  g_a);
    cudaGetSymbolAddress((void**)&f,  g_f);
    cudaGetSymbolAddress((void**)&wq, g_wq);
    cudaGetSymbolAddress((void**)&wo, g_wo);
    cudaGetSymbolAddress((void**)&w1, g_w1);
    cudaGetSymbolAddress((void**)&w2, g_w2);

    cudaFuncSetAttribute(attn_flash, cudaFuncAttributeMaxDynamicSharedMemorySize, ATT_SMEM);
    cudaFuncSetAttribute(tc_gemm<1>, cudaFuncAttributeMaxDynamicSharedMemorySize, GS_TOTAL);
    cudaFuncSetAttribute(tc_gemm<2>, cudaFuncAttributeMaxDynamicSharedMemorySize, GS_TOTAL);
    cudaFuncSetAttribute(tc_gemm<3>, cudaFuncAttributeMaxDynamicSharedMemorySize, GS_TOTAL);

    cvt_all_kernel<<<(CV_TOTAL + 255)/256, 256>>>(qkv_w, out_w, ff1_w, ff2_w,
                                                  wq, wo, w1, w2);

    inproj_kernel<<<ROWS, 128>>>(feat, proj_w, proj_b, pe, x, xa);

    for (int l = 0; l < NLAYER; l++) {
        // QKV -> fp16
        tc_gemm<3><<<dim3(3*Dm/128, ROWS/128), 128, GS_TOTAL>>>(
            xa, wq + (size_t)l*3*Dm*Dm, qkv_b + (size_t)l*3*Dm, nullptr,
            nullptr, q, ROWS, 3*Dm, Dm);
        // flash banded attention -> a (fp16)
        attn_flash<<<dim3(Tseq/64, Hh, Bsz), 128, ATT_SMEM>>>(q, a);
        // out proj + residual(x) -> y (fp32)
        tc_gemm<1><<<dim3(Dm/128, ROWS/128), 128, GS_TOTAL>>>(
            a, wo + (size_t)l*Dm*Dm, out_b + (size_t)l*Dm, x,
            y, nullptr, ROWS, Dm, Dm);
        ln_kernel<<<ROWS, 256>>>(y, ln1_g + (size_t)l*Dm, ln1_b + (size_t)l*Dm, x, xa);
        // FF1 + ReLU -> f (fp16)
        tc_gemm<2><<<dim3(FFd/128, ROWS/128), 128, GS_TOTAL>>>(
            xa, w1 + (size_t)l*FFd*Dm, ff1_b + (size_t)l*FFd, nullptr,
            nullptr, f, ROWS, FFd, Dm);
        // FF2 + residual(x) -> y (fp32)
        tc_gemm<1><<<dim3(Dm/128, ROWS/128), 128, GS_TOTAL>>>(
            f, w2 + (size_t)l*Dm*FFd, ff2_b + (size_t)l*Dm, x,
            y, nullptr, ROWS, Dm, FFd);
        if (l == NLAYER - 1)
            ln_kernel<<<ROWS, 256>>>(y, ln2_g + (size_t)l*Dm, ln2_b + (size_t)l*Dm,
                                     (float*)d_out, nullptr);
        else
            ln_kernel<<<ROWS, 256>>>(y, ln2_g + (size_t)l*Dm, ln2_b + (size_t)l*Dm, x, xa);
    }
}

// round 17
// speedup vs baseline: 1.0849x; 1.0074x over previous
#include <cuda_runtime.h>
#include <cuda_fp16.h>
#include <cstdint>
#include <cstddef>

#define Bsz 4
#define Tseq 2048
#define Dm 512
#define Hh 8
#define FFd 2048
#define NLAYER 4
#define ROWS (Bsz*Tseq)   /* 8192 */

// ---------------- scratch (device globals; no allocations allowed) ----------
__device__ __align__(128) float g_x [ROWS*Dm];
__device__ __align__(128) float g_y [ROWS*Dm];
__device__ __align__(128) __half g_q [ROWS*3*Dm];
__device__ __align__(128) __half g_xa[ROWS*Dm];
__device__ __align__(128) __half g_a [ROWS*Dm];
__device__ __align__(128) __half g_f [ROWS*FFd];
__device__ __align__(128) __half g_wq[NLAYER*3*Dm*Dm];
__device__ __align__(128) __half g_wo[NLAYER*Dm*Dm];
__device__ __align__(128) __half g_w1[NLAYER*FFd*Dm];
__device__ __align__(128) __half g_w2[NLAYER*Dm*FFd];

// ---------------- helpers ----------------------------------------------------
__device__ __forceinline__ void cp16(uint32_t s, const void* g) {
    asm volatile("cp.async.cg.shared.global [%0], [%1], 16;" :: "r"(s), "l"(g));
}
__device__ __forceinline__ void cp16z(uint32_t s, const void* g, int sz) {
    asm volatile("cp.async.cg.shared.global [%0], [%1], 16, %2;" :: "r"(s), "l"(g), "r"(sz));
}
__device__ __forceinline__ void cp_commit() {
    asm volatile("cp.async.commit_group;" ::: "memory");
}
template<int N> __device__ __forceinline__ void cp_wait() {
    asm volatile("cp.async.wait_group %0;" :: "n"(N) : "memory");
}
__device__ __forceinline__ void ldsm4(uint32_t* r, uint32_t addr) {
    asm volatile("ldmatrix.sync.aligned.m8n8.x4.shared.b16 {%0,%1,%2,%3}, [%4];"
                 : "=r"(r[0]), "=r"(r[1]), "=r"(r[2]), "=r"(r[3]) : "r"(addr));
}
__device__ __forceinline__ void ldsm4t(uint32_t* r, uint32_t addr) {
    asm volatile("ldmatrix.sync.aligned.m8n8.x4.trans.shared.b16 {%0,%1,%2,%3}, [%4];"
                 : "=r"(r[0]), "=r"(r[1]), "=r"(r[2]), "=r"(r[3]) : "r"(addr));
}
__device__ __forceinline__ void mma16816(float* c, const uint32_t* a, const uint32_t* b) {
    asm volatile(
        "mma.sync.aligned.m16n8k16.row.col.f32.f16.f16.f32 "
        "{%0,%1,%2,%3}, {%4,%5,%6,%7}, {%8,%9}, {%0,%1,%2,%3};"
        : "+f"(c[0]), "+f"(c[1]), "+f"(c[2]), "+f"(c[3])
        : "r"(a[0]), "r"(a[1]), "r"(a[2]), "r"(a[3]), "r"(b[0]), "r"(b[1]));
}
__device__ __forceinline__ uint32_t packh2(float a, float b) {
    __half2 h = __floats2half2_rn(a, b);
    return *(uint32_t*)&h;
}

// ---------------- fused weight fp32 -> fp16 convert (single launch) ----------
#define CV_WQ (NLAYER*3*Dm*Dm/4)
#define CV_WO (NLAYER*Dm*Dm/4)
#define CV_W1 (NLAYER*FFd*Dm/4)
#define CV_W2 (NLAYER*Dm*FFd/4)
#define CV_TOTAL (CV_WQ + CV_WO + CV_W1 + CV_W2)

__global__ __launch_bounds__(256)
void cvt_all_kernel(const float* __restrict__ wq, const float* __restrict__ wo,
                    const float* __restrict__ w1, const float* __restrict__ w2,
                    __half* __restrict__ dq, __half* __restrict__ do_,
                    __half* __restrict__ d1, __half* __restrict__ d2)
{
    int i = blockIdx.x * 256 + threadIdx.x;
    if (i >= CV_TOTAL) return;
    const float* src; __half* dst; int j;
    if (i < CV_WQ)                   { src = wq; dst = dq;  j = i; }
    else if (i < CV_WQ+CV_WO)        { src = wo; dst = do_; j = i - CV_WQ; }
    else if (i < CV_WQ+CV_WO+CV_W1)  { src = w1; dst = d1;  j = i - CV_WQ - CV_WO; }
    else                             { src = w2; dst = d2;  j = i - CV_WQ - CV_WO - CV_W1; }
    float4 v = ((const float4*)src)[j];
    ((__half2*)dst)[j*2]     = __floats2half2_rn(v.x, v.y);
    ((__half2*)dst)[j*2 + 1] = __floats2half2_rn(v.z, v.w);
}

// ---------------- HMMA GEMM: C[M,N] = A[M,K] @ W[N,K]^T ----------------------
// BM=128, BN=128, BK=64, 128 threads (4 warps, warp tile 64x64), 3-stage
// cp.async, 2 CTAs/SM, software-pipelined fragment double-buffering.
// MODE 1: Cf = acc + bias + res  (fp32 out)
// MODE 2: Ch = fp16(relu(acc + bias))
// MODE 3: Ch = fp16(acc + bias)
#define AROW 144
#define A_TILE (128*AROW)
#define B_TILE (128*AROW)
#define STAGE_B (A_TILE + B_TILE)
#define NSTAGE 3
#define GS_TOTAL (NSTAGE*STAGE_B)   /* 110592 per CTA */

__device__ __forceinline__ void gload(uint32_t st,
    const __half* __restrict__ A, const __half* __restrict__ B,
    int bm, int bn, int K, int k0, int tid)
{
    #pragma unroll
    for (int i = 0; i < 8; i++) {
        int idx = tid + i * 128;
        int row = idx >> 3, c = idx & 7;
        cp16(st + (uint32_t)(row * AROW + c * 16), A + (size_t)(bm + row) * K + k0 + c * 8);
    }
    #pragma unroll
    for (int i = 0; i < 8; i++) {
        int idx = tid + i * 128;
        int row = idx >> 3, c = idx & 7;
        cp16(st + A_TILE + (uint32_t)(row * AROW + c * 16), B + (size_t)(bn + row) * K + k0 + c * 8);
    }
    cp_commit();
}

template<int MODE>
__global__ __launch_bounds__(128, 2)
void tc_gemm(const __half* __restrict__ A, const __half* __restrict__ B,
             const float* __restrict__ bias, const float* __restrict__ res,
             float* __restrict__ Cf, __half* __restrict__ Ch,
             int M, int N, int K)
{
    extern __shared__ __align__(128) char smem[];
    uint32_t sb = (uint32_t)__cvta_generic_to_shared(smem);
    int tid = threadIdx.x;
    int wid = tid >> 5, lane = tid & 31;
    int bn = blockIdx.x * 128, bm = blockIdx.y * 128;
    int wm = (wid & 1) * 64;
    int wn = (wid >> 1) * 64;

    float acc[4][8][4];
    #pragma unroll
    for (int i = 0; i < 4; i++)
        #pragma unroll
        for (int j = 0; j < 8; j++)
            #pragma unroll
            for (int r = 0; r < 4; r++) acc[i][j][r] = 0.f;

    const int C = K >> 6;
    gload(sb,           A, B, bm, bn, K, 0,  tid);
    gload(sb + STAGE_B, A, B, bm, bn, K, 64, tid);

    uint32_t a_row = (uint32_t)(lane & 15);
    uint32_t a_koff = (uint32_t)((lane >> 4) * 16);
    uint32_t b_row = (uint32_t)((lane & 7) + ((lane >> 4) << 3));
    uint32_t b_koff = (uint32_t)(((lane >> 3) & 1) * 16);

    uint32_t afb[2][4][4], bfb[2][4][4];

    for (int c = 0; c < C; c++) {
        if (c + 1 < C) cp_wait<1>(); else cp_wait<0>();
        __syncthreads();
        if (c + 2 < C)
            gload(sb + ((c + 2) % NSTAGE) * STAGE_B, A, B, bm, bn, K, (c + 2) * 64, tid);

        uint32_t sa = sb + (c % NSTAGE) * STAGE_B;

        #pragma unroll
        for (int mt = 0; mt < 4; mt++)
            ldsm4(afb[0][mt], sa + (wm + mt*16 + a_row) * AROW + a_koff);
        #pragma unroll
        for (int ng = 0; ng < 4; ng++)
            ldsm4(bfb[0][ng], sa + A_TILE + (wn + ng*16 + b_row) * AROW + b_koff);

        #pragma unroll
        for (int kk = 0; kk < 4; kk++) {
            int cur = kk & 1, nxt = cur ^ 1;
            if (kk < 3) {
                uint32_t kb = (uint32_t)((kk + 1) * 32);
                #pragma unroll
                for (int mt = 0; mt < 4; mt++)
                    ldsm4(afb[nxt][mt], sa + (wm + mt*16 + a_row) * AROW + kb + a_koff);
                #pragma unroll
                for (int ng = 0; ng < 4; ng++)
                    ldsm4(bfb[nxt][ng], sa + A_TILE + (wn + ng*16 + b_row) * AROW + kb + b_koff);
            }
            #pragma unroll
            for (int ng = 0; ng < 4; ng++)
                #pragma unroll
                for (int mt = 0; mt < 4; mt++)
                    #pragma unroll
                    for (int half = 0; half < 2; half++)
                        mma16816(acc[mt][ng*2 + half], afb[cur][mt], &bfb[cur][ng][half*2]);
        }
    }

    #pragma unroll
    for (int mt = 0; mt < 4; mt++) {
        int m0 = bm + wm + mt*16 + (lane >> 2);
        #pragma unroll
        for (int nt = 0; nt < 8; nt++) {
            int n = bn + wn + nt*8 + (lane & 3)*2;
            float bx = bias[n], by = bias[n+1];
            #pragma unroll
            for (int h = 0; h < 2; h++) {
                int m = m0 + h*8;
                float v0 = acc[mt][nt][h*2]   + bx;
                float v1 = acc[mt][nt][h*2+1] + by;
                size_t idx = (size_t)m * N + n;
                if (MODE == 1) {
                    float2 rv = *(const float2*)&res[idx];
                    v0 += rv.x; v1 += rv.y;
                    *(float2*)&Cf[idx] = make_float2(v0, v1);
                } else {
                    if (MODE == 2) { v0 = fmaxf(v0, 0.f); v1 = fmaxf(v1, 0.f); }
                    *(__half2*)(Ch + idx) = __floats2half2_rn(v0, v1);
                }
            }
        }
    }
}

// ---------------- flash banded attention (fp16, register softmax) ------------
// __launch_bounds__(128,4): force reg cap ~124 for 4-CTA/SM residency.
#define OFF_Q  0
#define OFF_K0 9216
#define OFF_V0 18432
#define OFF_K1 27648
#define OFF_V1 36864
#define ATT_SMEM 46080
#define QROW 144

__global__ __launch_bounds__(128, 4)
void attn_flash(const __half* __restrict__ q, __half* __restrict__ outp)
{
    extern __shared__ __align__(128) char smraw[];
    uint32_t sb = (uint32_t)__cvta_generic_to_shared(smraw);

    int tid = threadIdx.x;
    int wid = tid >> 5, lane = tid & 31;
    int b = blockIdx.z, h = blockIdx.y;
    int qstart = blockIdx.x << 6;
    size_t rowbase = (size_t)b * Tseq;
    int wm = wid * 16;
    bool edge_tile = (qstart < 128) || (qstart + 320 > Tseq);

    uint32_t a_row = (uint32_t)(lane & 15);
    uint32_t a_koff = (uint32_t)((lane >> 4) * 16);
    uint32_t b_row = (uint32_t)((lane & 7) + ((lane >> 4) << 3));
    uint32_t b_koff = (uint32_t)(((lane >> 3) & 1) * 16);

    int fi = tid >> 3;
    int seg = tid & 7;

    #pragma unroll
    for (int r = 0; r < 4; r++) {
        int qi = fi + r*16;
        cp16(sb + OFF_Q + qi*QROW + seg*16,
             q + (rowbase + qstart + qi)*1536 + h*64 + seg*8);
    }
    #pragma unroll
    for (int r = 0; r < 4; r++) {
        int kj = fi + r*16;
        int ka = qstart - 128 + kj;
        int kc = ka < 0 ? 0 : (ka >= Tseq ? Tseq-1 : ka);
        int ok = (ka >= 0 && ka < Tseq) ? 16 : 0;
        cp16z(sb + OFF_K0 + kj*QROW + seg*16,
              q + (rowbase + kc)*1536 + 512 + h*64 + seg*8, ok);
        cp16z(sb + OFF_V0 + kj*QROW + seg*16,
              q + (rowbase + kc)*1536 + 1024 + h*64 + seg*8, ok);
    }
    cp_commit();

    const float scale = 0.125f;
    uint32_t af[4][4];
    float m_run[2] = {-1e30f, -1e30f};
    float l_run[2] = {0.f, 0.f};
    float oacc[8][4];
    #pragma unroll
    for (int nt = 0; nt < 8; nt++)
        #pragma unroll
        for (int r = 0; r < 4; r++) oacc[nt][r] = 0.f;

    for (int kb = 0; kb < 5; kb++) {
        cp_wait<0>();
        __syncthreads();
        if (kb == 0) {
            #pragma unroll
            for (int ks = 0; ks < 4; ks++)
                ldsm4(af[ks], sb + OFF_Q + (wm + a_row)*QROW + ks*32 + a_koff);
        }
        if (kb < 4) {
            uint32_t kd = (kb + 1) & 1 ? OFF_K1 : OFF_K0;
            uint32_t vd = (kb + 1) & 1 ? OFF_V1 : OFF_V0;
            #pragma unroll
            for (int r = 0; r < 4; r++) {
                int kj = fi + r*16;
                int ka = qstart - 128 + (kb+1)*64 + kj;
                int kc = ka < 0 ? 0 : (ka >= Tseq ? Tseq-1 : ka);
                int ok = (ka >= 0 && ka < Tseq) ? 16 : 0;
                cp16z(sb + kd + kj*QROW + seg*16,
                      q + (rowbase + kc)*1536 + 512 + h*64 + seg*8, ok);
                cp16z(sb + vd + kj*QROW + seg*16,
                      q + (rowbase + kc)*1536 + 1024 + h*64 + seg*8, ok);
            }
            cp_commit();
        }

        uint32_t kbuf = sb + (kb & 1 ? OFF_K1 : OFF_K0);
        uint32_t vbuf = sb + (kb & 1 ? OFF_V1 : OFF_V0);

        float sacc[8][4];
        #pragma unroll
        for (int nt = 0; nt < 8; nt++)
            #pragma unroll
            for (int r = 0; r < 4; r++) sacc[nt][r] = 0.f;

        #pragma unroll
        for (int ks = 0; ks < 4; ks++) {
            #pragma unroll
            for (int ng = 0; ng < 4; ng++) {
                uint32_t bf[4];
                ldsm4(bf, kbuf + (ng*16 + b_row)*QROW + ks*32 + b_koff);
                mma16816(sacc[ng*2],     af[ks], bf);
                mma16816(sacc[ng*2 + 1], af[ks], &bf[2]);
            }
        }

        bool need_mask = (kb == 0) | (kb >= 3) | edge_tile;
        if (need_mask) {
            #pragma unroll
            for (int nt = 0; nt < 8; nt++)
                #pragma unroll
                for (int r = 0; r < 4; r++) {
                    int qi   = wm + (lane >> 2) + (r >> 1)*8;
                    int kidx = kb*64 + nt*8 + (lane & 3)*2 + (r & 1);
                    int ka   = qstart - 128 + kidx;
                    int delta = kidx - qi;
                    bool ok = (delta >= 0) && (delta <= 256) && (ka >= 0) && (ka < Tseq);
                    sacc[nt][r] = ok ? sacc[nt][r] * scale : -1e30f;
                }
        } else {
            #pragma unroll
            for (int nt = 0; nt < 8; nt++)
                #pragma unroll
                for (int r = 0; r < 4; r++)
                    sacc[nt][r] *= scale;
        }

        #pragma unroll
        for (int hr = 0; hr < 2; hr++) {
            float mb = -1e30f;
            #pragma unroll
            for (int nt = 0; nt < 8; nt++) {
                mb = fmaxf(mb, sacc[nt][hr*2]);
                mb = fmaxf(mb, sacc[nt][hr*2 + 1]);
            }
            mb = fmaxf(mb, __shfl_xor_sync(0xffffffffu, mb, 1));
            mb = fmaxf(mb, __shfl_xor_sync(0xffffffffu, mb, 2));
            float m_new = fmaxf(m_run[hr], mb);
            float factor = __expf(m_run[hr] - m_new);
            float psum = 0.f;
            #pragma unroll
            for (int nt = 0; nt < 8; nt++)
                #pragma unroll
                for (int j = 0; j < 2; j++) {
                    float s = sacc[nt][hr*2 + j];
                    float p = (s > -1e29f) ? __expf(s - m_new) : 0.f;
                    sacc[nt][hr*2 + j] = p;
                    psum += p;
                }
            psum += __shfl_xor_sync(0xffffffffu, psum, 1);
            psum += __shfl_xor_sync(0xffffffffu, psum, 2);
            l_run[hr] = l_run[hr] * factor + psum;
            m_run[hr] = m_new;
            #pragma unroll
            for (int nt = 0; nt < 8; nt++)
                #pragma unroll
                for (int j = 0; j < 2; j++)
                    oacc[nt][hr*2 + j] *= factor;
        }

        uint32_t pf[4][4];
        #pragma unroll
        for (int ks = 0; ks < 4; ks++) {
            pf[ks][0] = packh2(sacc[2*ks][0],     sacc[2*ks][1]);
            pf[ks][1] = packh2(sacc[2*ks][2],     sacc[2*ks][3]);
            pf[ks][2] = packh2(sacc[2*ks + 1][0], sacc[2*ks + 1][1]);
            pf[ks][3] = packh2(sacc[2*ks + 1][2], sacc[2*ks + 1][3]);
        }

        #pragma unroll
        for (int ks = 0; ks < 4; ks++) {
            #pragma unroll
            for (int dn = 0; dn < 4; dn++) {
                uint32_t bf[4];
                ldsm4t(bf, vbuf + (ks*16 + a_row)*QROW + dn*32 + a_koff);
                mma16816(oacc[dn*2],     pf[ks], bf);
                mma16816(oacc[dn*2 + 1], pf[ks], &bf[2]);
            }
        }
    }

    #pragma unroll
    for (int hr = 0; hr < 2; hr++) {
        float rs = 1.0f / l_run[hr];
        int qi = qstart + wm + (lane >> 2) + hr*8;
        #pragma unroll
        for (int nt = 0; nt < 8; nt++) {
            int d = nt*8 + (lane & 3)*2;
            size_t idx = (rowbase + qi)*512 + h*64 + d;
            *(__half2*)(outp + idx) =
                __floats2half2_rn(oacc[nt][hr*2] * rs, oacc[nt][hr*2 + 1] * rs);
        }
    }
}

// ---------------- LayerNorm (fp32 in; fp32 out + optional fp16 out) ----------
__global__ __launch_bounds__(256)
void ln_kernel(const float* __restrict__ in, const float* __restrict__ gam,
               const float* __restrict__ bet, float* __restrict__ out,
               __half* __restrict__ oh)
{
    int row = blockIdx.x, tid = threadIdx.x;
    const float* p = in + (size_t)row * 512;
    float x0 = p[tid], x1 = p[tid + 256];
    float s = x0 + x1, q = x0*x0 + x1*x1;
    #pragma unroll
    for (int o = 16; o > 0; o >>= 1) {
        s += __shfl_xor_sync(0xffffffffu, s, o);
        q += __shfl_xor_sync(0xffffffffu, q, o);
    }
    __shared__ float ss[8], sq[8];
    int w = tid >> 5, l = tid & 31;
    if (l == 0) { ss[w] = s; sq[w] = q; }
    __syncthreads();
    float ts = 0.f, tq = 0.f;
    #pragma unroll
    for (int i = 0; i < 8; i++) { ts += ss[i]; tq += sq[i]; }
    float mean = ts * (1.0f/512.0f);
    float var  = tq * (1.0f/512.0f) - mean*mean;
    float inv  = rsqrtf(var + 1e-5f);
    float v0 = (x0 - mean) * inv * gam[tid]       + bet[tid];
    float v1 = (x1 - mean) * inv * gam[tid + 256] + bet[tid + 256];
    float* o = out + (size_t)row * 512;
    o[tid]       = v0;
    o[tid + 256] = v1;
    if (oh) {
        oh[(size_t)row*512 + tid]       = __float2half(v0);
        oh[(size_t)row*512 + tid + 256] = __float2half(v1);
    }
}

// ---------------- input projection ------------------------------------------
__global__ __launch_bounds__(128)
void inproj_kernel(const float* __restrict__ feat, const float* __restrict__ w,
                   const float* __restrict__ bias, const float* __restrict__ pe,
                   float* __restrict__ out, __half* __restrict__ oh)
{
    int row = blockIdx.x;
    int t = row & (Tseq - 1);
    __shared__ float f[32];
    if (threadIdx.x < 32) f[threadIdx.x] = feat[(size_t)row*32 + threadIdx.x];
    __syncthreads();
    int d0 = threadIdx.x * 4;
    float a[4];
    #pragma unroll
    for (int j = 0; j < 4; j++) a[j] = bias[d0 + j];
    #pragma unroll
    for (int j = 0; j < 4; j++) {
        const float4* wp = (const float4*)(w + (size_t)(d0 + j) * 32);
        #pragma unroll
        for (int k4 = 0; k4 < 8; k4++) {
            float4 wv = wp[k4];
            a[j] += wv.x*f[k4*4] + wv.y*f[k4*4+1] + wv.z*f[k4*4+2] + wv.w*f[k4*4+3];
        }
    }
    float4 pev = *(const float4*)(pe + (size_t)t*512 + d0);
    float4 r = make_float4(a[0]+pev.x, a[1]+pev.y, a[2]+pev.z, a[3]+pev.w);
    *(float4*)(out + (size_t)row*512 + d0) = r;
    *(__half2*)(oh + (size_t)row*512 + d0)     = __floats2half2_rn(r.x, r.y);
    *(__half2*)(oh + (size_t)row*512 + d0 + 2) = __floats2half2_rn(r.z, r.w);
}

// ---------------- launch ----------------------------------------------------
extern "C" void kernel_launch(void* const* d_in, const int* in_sizes, int n_in,
                              void* d_out, int out_size)
{
    const float* feat   = (const float*)d_in[0];
    const float* proj_w = (const float*)d_in[2];
    const float* proj_b = (const float*)d_in[3];
    const float* pe     = (const float*)d_in[4];
    const float* qkv_w  = (const float*)d_in[5];
    const float* qkv_b  = (const float*)d_in[6];
    const float* out_w  = (const float*)d_in[7];
    const float* out_b  = (const float*)d_in[8];
    const float* ff1_w  = (const float*)d_in[9];
    const float* ff1_b  = (const float*)d_in[10];
    const float* ff2_w  = (const float*)d_in[11];
    const float* ff2_b  = (const float*)d_in[12];
    const float* ln1_g  = (const float*)d_in[13];
    const float* ln1_b  = (const float*)d_in[14];
    const float* ln2_g  = (const float*)d_in[15];
    const float* ln2_b  = (const float*)d_in[16];

    float *x, *y;
    __half *q, *xa, *a, *f, *wq, *wo, *w1, *w2;
    cudaGetSymbolAddress((void**)&x,  g_x);
    cudaGetSymbolAddress((void**)&y,  g_y);
    cudaGetSymbolAddress((void**)&q,  g_q);
    cudaGetSymbolAddress((void**)&xa, g_xa);
    cudaGetSymbolAddress((void**)&a,  g_a);
    cudaGetSymbolAddress((void**)&f,  g_f);
    cudaGetSymbolAddress((void**)&wq, g_wq);
    cudaGetSymbolAddress((void**)&wo, g_wo);
    cudaGetSymbolAddress((void**)&w1, g_w1);
    cudaGetSymbolAddress((void**)&w2, g_w2);

    cudaFuncSetAttribute(attn_flash, cudaFuncAttributeMaxDynamicSharedMemorySize, ATT_SMEM);
    cudaFuncSetAttribute(tc_gemm<1>, cudaFuncAttributeMaxDynamicSharedMemorySize, GS_TOTAL);
    cudaFuncSetAttribute(tc_gemm<2>, cudaFuncAttributeMaxDynamicSharedMemorySize, GS_TOTAL);
    cudaFuncSetAttribute(tc_gemm<3>, cudaFuncAttributeMaxDynamicSharedMemorySize, GS_TOTAL);

    cvt_all_kernel<<<(CV_TOTAL + 255)/256, 256>>>(qkv_w, out_w, ff1_w, ff2_w,
                                                  wq, wo, w1, w2);

    inproj_kernel<<<ROWS, 128>>>(feat, proj_w, proj_b, pe, x, xa);

    for (int l = 0; l < NLAYER; l++) {
        // QKV -> fp16
        tc_gemm<3><<<dim3(3*Dm/128, ROWS/128), 128, GS_TOTAL>>>(
            xa, wq + (size_t)l*3*Dm*Dm, qkv_b + (size_t)l*3*Dm, nullptr,
            nullptr, q, ROWS, 3*Dm, Dm);
        // flash banded attention -> a (fp16)
        attn_flash<<<dim3(Tseq/64, Hh, Bsz), 128, ATT_SMEM>>>(q, a);
        // out proj + residual(x) -> y (fp32)
        tc_gemm<1><<<dim3(Dm/128, ROWS/128), 128, GS_TOTAL>>>(
            a, wo + (size_t)l*Dm*Dm, out_b + (size_t)l*Dm, x,
            y, nullptr, ROWS, Dm, Dm);
        ln_kernel<<<ROWS, 256>>>(y, ln1_g + (size_t)l*Dm, ln1_b + (size_t)l*Dm, x, xa);
        // FF1 + ReLU -> f (fp16)
        tc_gemm<2><<<dim3(FFd/128, ROWS/128), 128, GS_TOTAL>>>(
            xa, w1 + (size_t)l*FFd*Dm, ff1_b + (size_t)l*FFd, nullptr,
            nullptr, f, ROWS, FFd, Dm);
        // FF2 + residual(x) -> y (fp32)
        tc_gemm<1><<<dim3(Dm/128, ROWS/128), 128, GS_TOTAL>>>(
            f, w2 + (size_t)l*Dm*FFd, ff2_b + (size_t)l*Dm, x,
            y, nullptr, ROWS, Dm, FFd);
        if (l == NLAYER - 1)
            ln_kernel<<<ROWS, 256>>>(y, ln2_g + (size_t)l*Dm, ln2_b + (size_t)l*Dm,
                                     (float*)d_out, nullptr);
        else
            ln_kernel<<<ROWS, 256>>>(y, ln2_g + (size_t)l*Dm, ln2_b + (size_t)l*Dm, x, xa);
    }
}